// round 10
// baseline (speedup 1.0000x reference)
#include <cuda_runtime.h>
#include <math.h>

#define N_NODES 100000
#define E_EDGES 800000
#define G_GRAPHS 512
#define HID 32
#define D_CUT 5.0f
#define TAB 2048
#define NODE_BLOCKS 1563   // ceil(100000/64)

typedef unsigned long long u64;

// ---------------- scratch (static, no allocation) ----------------
__device__ __align__(16) float g_ss[G_GRAPHS * 64];
__device__ __align__(16) float g_xm[N_NODES * 32];
__device__ __align__(16) float g_a[N_NODES * 32];
__device__ __align__(16) float g_b[N_NODES * 32];
__device__ __align__(16) float g_gate[N_NODES * 32];
__device__ __align__(16) float g_macc[N_NODES * 32];
__device__ __align__(16) float g_pacc[N_NODES * 4];
__device__ __align__(16) float4 g_pos4[N_NODES];
__device__ __align__(16) float g_tab[TAB * 32];
__device__ __align__(16) float g_m[E_EDGES * 32];   // per-edge message (kE1 -> kE2)
__device__ __align__(16) float4 g_dv[E_EDGES];      // per-edge pos_diff

__device__ __forceinline__ float siluf(float v) { return v / (1.0f + __expf(-v)); }
__device__ __forceinline__ float sigmf(float v) { return 1.0f / (1.0f + __expf(-v)); }

__device__ __forceinline__ void red_v4(float* p, float a, float b, float c, float d) {
    asm volatile("red.global.add.v4.f32 [%0], {%1,%2,%3,%4};"
                 :: "l"(p), "f"(a), "f"(b), "f"(c), "f"(d) : "memory");
}

__device__ __forceinline__ u64 pack2(float lo, float hi) {
    u64 r; asm("mov.b64 %0, {%1, %2};" : "=l"(r) : "f"(lo), "f"(hi)); return r;
}
__device__ __forceinline__ void unpack2(u64 v, float& lo, float& hi) {
    asm("mov.b64 {%0, %1}, %2;" : "=f"(lo), "=f"(hi) : "l"(v));
}
__device__ __forceinline__ void ffma2(u64& d, u64 a, u64 b) {
    asm("fma.rn.f32x2 %0, %1, %2, %0;" : "+l"(d) : "l"(a), "l"(b));
}

// ---------------- K1: time MLP + dist_emb table (fused) ----------------
__global__ void __launch_bounds__(256) k_time(
        const float* __restrict__ time,
        const float* __restrict__ w1, const float* __restrict__ b1,
        const float* __restrict__ w2, const float* __restrict__ b2,
        const float* __restrict__ means, const float* __restrict__ betas,
        const float* __restrict__ w_dist) {
    int tid = threadIdx.x;
    if (blockIdx.x >= G_GRAPHS / 4) {
        __shared__ float sW[1024];
        __shared__ float sMu[32], sBeta[32];
        for (int k = tid; k < 1024; k += 256) sW[k] = w_dist[k];
        if (tid < 32) { sMu[tid] = means[tid]; sBeta[tid] = betas[tid]; }
        __syncthreads();
        int r = (blockIdx.x - G_GRAPHS / 4) * 8 + (tid >> 5);
        int c = tid & 31;
        float d = (float)r * (D_CUT / (float)(TAB - 1));
        float cutoff = 0.5f * (__cosf(d * (3.14159265358979f / D_CUT)) + 1.0f);
        float ed = __expf(-d);
        float acc = 0.0f;
        #pragma unroll 8
        for (int k = 0; k < 32; k++) {
            float t = ed - sMu[k];
            acc += __expf(-sBeta[k] * t * t) * sW[k * 32 + c];
        }
        g_tab[r * 32 + c] = cutoff * acc;
        return;
    }
    __shared__ float trow[4][128];
    __shared__ float hid[4][64];
    int gsub = tid >> 6;
    int t = tid & 63;
    int g = blockIdx.x * 4 + gsub;
    trow[gsub][t]      = time[g * 128 + t];
    trow[gsub][t + 64] = time[g * 128 + 64 + t];
    __syncthreads();
    float acc = b1[t];
    #pragma unroll 8
    for (int k = 0; k < 128; k++) acc += trow[gsub][k] * w1[k * 64 + t];
    hid[gsub][t] = siluf(acc);
    __syncthreads();
    float acc2 = b2[t];
    #pragma unroll 8
    for (int k = 0; k < 64; k++) acc2 += hid[gsub][k] * w2[k * 64 + t];
    g_ss[g * 64 + t] = acc2;
}

// ---------------- K2: per-node precompute, NE=2 nodes per 4-lane group ------
__global__ void __launch_bounds__(128) k_node(
        const float* __restrict__ x, const int* __restrict__ batch,
        const float* __restrict__ pos,
        const float* __restrict__ msg_w1, const float* __restrict__ msg_b1,
        const float* __restrict__ gate_w, const float* __restrict__ gate_b) {
    __shared__ __align__(16) float sW1[64 * 32];
    __shared__ __align__(16) float sWg[32 * 32];
    int tid = threadIdx.x;
    for (int k = tid; k < 2048; k += 128) sW1[k] = msg_w1[k];
    for (int k = tid; k < 1024; k += 128) sWg[k] = gate_w[k];
    __syncthreads();

    int sub = tid & 3;
    int c0 = sub * 8;
    int n0 = blockIdx.x * 64 + (tid >> 2) * 2;
    if (n0 >= N_NODES) return;   // warp-uniform: 16 nodes/warp, 16 | 100000
    int n1 = n0 + 1;

    float xmA[8], xmB[8];
    {
        int bn = batch[n0];
        const float4* scp = (const float4*)&g_ss[bn * 64 + c0];
        const float4* shp = (const float4*)&g_ss[bn * 64 + 32 + c0];
        const float4* xp  = (const float4*)&x[n0 * 32 + c0];
        float4 sc0 = scp[0], sc1 = scp[1];
        float4 sh0 = shp[0], sh1 = shp[1];
        float4 x0 = xp[0], x1 = xp[1];
        xmA[0] = siluf(x0.x * (1.0f + sc0.x) + sh0.x);
        xmA[1] = siluf(x0.y * (1.0f + sc0.y) + sh0.y);
        xmA[2] = siluf(x0.z * (1.0f + sc0.z) + sh0.z);
        xmA[3] = siluf(x0.w * (1.0f + sc0.w) + sh0.w);
        xmA[4] = siluf(x1.x * (1.0f + sc1.x) + sh1.x);
        xmA[5] = siluf(x1.y * (1.0f + sc1.y) + sh1.y);
        xmA[6] = siluf(x1.z * (1.0f + sc1.z) + sh1.z);
        xmA[7] = siluf(x1.w * (1.0f + sc1.w) + sh1.w);
    }
    {
        int bn = batch[n1];
        const float4* scp = (const float4*)&g_ss[bn * 64 + c0];
        const float4* shp = (const float4*)&g_ss[bn * 64 + 32 + c0];
        const float4* xp  = (const float4*)&x[n1 * 32 + c0];
        float4 sc0 = scp[0], sc1 = scp[1];
        float4 sh0 = shp[0], sh1 = shp[1];
        float4 x0 = xp[0], x1 = xp[1];
        xmB[0] = siluf(x0.x * (1.0f + sc0.x) + sh0.x);
        xmB[1] = siluf(x0.y * (1.0f + sc0.y) + sh0.y);
        xmB[2] = siluf(x0.z * (1.0f + sc0.z) + sh0.z);
        xmB[3] = siluf(x0.w * (1.0f + sc0.w) + sh0.w);
        xmB[4] = siluf(x1.x * (1.0f + sc1.x) + sh1.x);
        xmB[5] = siluf(x1.y * (1.0f + sc1.y) + sh1.y);
        xmB[6] = siluf(x1.z * (1.0f + sc1.z) + sh1.z);
        xmB[7] = siluf(x1.w * (1.0f + sc1.w) + sh1.w);
    }

    u64 aA[4], bA[4], gA[4], aB[4], bB[4], gB[4];
    #pragma unroll
    for (int p = 0; p < 4; p++) {
        u64 mb = pack2(msg_b1[c0 + 2 * p], msg_b1[c0 + 2 * p + 1]);
        u64 gb = pack2(gate_b[c0 + 2 * p], gate_b[c0 + 2 * p + 1]);
        aA[p] = mb; aB[p] = mb;
        bA[p] = 0ULL; bB[p] = 0ULL;
        gA[p] = gb; gB[p] = gb;
    }
    #pragma unroll
    for (int kk = 0; kk < 32; kk++) {
        float vA = __shfl_sync(0xffffffffu, xmA[kk & 7], kk >> 3, 4);
        float vB = __shfl_sync(0xffffffffu, xmB[kk & 7], kk >> 3, 4);
        u64 vvA = pack2(vA, vA);
        u64 vvB = pack2(vB, vB);
        const ulonglong2* wa = (const ulonglong2*)&sW1[kk * 32 + c0];
        const ulonglong2* wb = (const ulonglong2*)&sW1[(32 + kk) * 32 + c0];
        const ulonglong2* wg = (const ulonglong2*)&sWg[kk * 32 + c0];
        ulonglong2 wa0 = wa[0], wa1 = wa[1];
        ulonglong2 wb0 = wb[0], wb1 = wb[1];
        ulonglong2 wg0 = wg[0], wg1 = wg[1];
        ffma2(aA[0], wa0.x, vvA); ffma2(aA[1], wa0.y, vvA);
        ffma2(aA[2], wa1.x, vvA); ffma2(aA[3], wa1.y, vvA);
        ffma2(aB[0], wa0.x, vvB); ffma2(aB[1], wa0.y, vvB);
        ffma2(aB[2], wa1.x, vvB); ffma2(aB[3], wa1.y, vvB);
        ffma2(bA[0], wb0.x, vvA); ffma2(bA[1], wb0.y, vvA);
        ffma2(bA[2], wb1.x, vvA); ffma2(bA[3], wb1.y, vvA);
        ffma2(bB[0], wb0.x, vvB); ffma2(bB[1], wb0.y, vvB);
        ffma2(bB[2], wb1.x, vvB); ffma2(bB[3], wb1.y, vvB);
        ffma2(gA[0], wg0.x, vvA); ffma2(gA[1], wg0.y, vvA);
        ffma2(gA[2], wg1.x, vvA); ffma2(gA[3], wg1.y, vvA);
        ffma2(gB[0], wg0.x, vvB); ffma2(gB[1], wg0.y, vvB);
        ffma2(gB[2], wg1.x, vvB); ffma2(gB[3], wg1.y, vvB);
    }

    {
        float4* oxm = (float4*)&g_xm[n0 * 32 + c0];
        oxm[0] = make_float4(xmA[0], xmA[1], xmA[2], xmA[3]);
        oxm[1] = make_float4(xmA[4], xmA[5], xmA[6], xmA[7]);
        ulonglong2* oa = (ulonglong2*)&g_a[n0 * 32 + c0];
        oa[0] = make_ulonglong2(aA[0], aA[1]); oa[1] = make_ulonglong2(aA[2], aA[3]);
        ulonglong2* ob = (ulonglong2*)&g_b[n0 * 32 + c0];
        ob[0] = make_ulonglong2(bA[0], bA[1]); ob[1] = make_ulonglong2(bA[2], bA[3]);
        float gg[8];
        unpack2(gA[0], gg[0], gg[1]); unpack2(gA[1], gg[2], gg[3]);
        unpack2(gA[2], gg[4], gg[5]); unpack2(gA[3], gg[6], gg[7]);
        float4* og = (float4*)&g_gate[n0 * 32 + c0];
        og[0] = make_float4(sigmf(gg[0]), sigmf(gg[1]), sigmf(gg[2]), sigmf(gg[3]));
        og[1] = make_float4(sigmf(gg[4]), sigmf(gg[5]), sigmf(gg[6]), sigmf(gg[7]));
    }
    {
        float4* oxm = (float4*)&g_xm[n1 * 32 + c0];
        oxm[0] = make_float4(xmB[0], xmB[1], xmB[2], xmB[3]);
        oxm[1] = make_float4(xmB[4], xmB[5], xmB[6], xmB[7]);
        ulonglong2* oa = (ulonglong2*)&g_a[n1 * 32 + c0];
        oa[0] = make_ulonglong2(aB[0], aB[1]); oa[1] = make_ulonglong2(aB[2], aB[3]);
        ulonglong2* ob = (ulonglong2*)&g_b[n1 * 32 + c0];
        ob[0] = make_ulonglong2(bB[0], bB[1]); ob[1] = make_ulonglong2(bB[2], bB[3]);
        float gg[8];
        unpack2(gB[0], gg[0], gg[1]); unpack2(gB[1], gg[2], gg[3]);
        unpack2(gB[2], gg[4], gg[5]); unpack2(gB[3], gg[6], gg[7]);
        float4* og = (float4*)&g_gate[n1 * 32 + c0];
        og[0] = make_float4(sigmf(gg[0]), sigmf(gg[1]), sigmf(gg[2]), sigmf(gg[3]));
        og[1] = make_float4(sigmf(gg[4]), sigmf(gg[5]), sigmf(gg[6]), sigmf(gg[7]));
    }

    float4 z = make_float4(0.f, 0.f, 0.f, 0.f);
    float4* mzA = (float4*)&g_macc[n0 * 32 + c0];
    mzA[0] = z; mzA[1] = z;
    float4* mzB = (float4*)&g_macc[n1 * 32 + c0];
    mzB[0] = z; mzB[1] = z;
    if (sub == 0) {
        *(float4*)&g_pacc[n0 * 4] = z;
        *(float4*)&g_pacc[n1 * 4] = z;
        g_pos4[n0] = make_float4(pos[n0 * 3], pos[n0 * 3 + 1], pos[n0 * 3 + 2], 0.0f);
        g_pos4[n1] = make_float4(pos[n1 * 3], pos[n1 * 3 + 1], pos[n1 * 3 + 2], 0.0f);
    }
}

#define MV32X2(accA, accB, inA, inB, W, c0)                                      \
    do {                                                                         \
        _Pragma("unroll")                                                        \
        for (int kk = 0; kk < 32; kk++) {                                        \
            float vA = __shfl_sync(0xffffffffu, inA[kk & 7], kk >> 3, 4);        \
            float vB = __shfl_sync(0xffffffffu, inB[kk & 7], kk >> 3, 4);        \
            u64 vvA = pack2(vA, vA);                                             \
            u64 vvB = pack2(vB, vB);                                             \
            const ulonglong2* wp = (const ulonglong2*)&W[kk * 32 + c0];          \
            ulonglong2 w0 = wp[0], w1 = wp[1];                                   \
            ffma2(accA[0], w0.x, vvA); ffma2(accA[1], w0.y, vvA);                \
            ffma2(accA[2], w1.x, vvA); ffma2(accA[3], w1.y, vvA);                \
            ffma2(accB[0], w0.x, vvB); ffma2(accB[1], w0.y, vvB);                \
            ffma2(accB[2], w1.x, vvB); ffma2(accB[3], w1.y, vvB);                \
        }                                                                        \
    } while (0)

// ---------------- K3a: message kernel (gathers + MV1 + m + scatter) ---------
__global__ void __launch_bounds__(128) k_edge1(
        const int* __restrict__ ei,
        const float* __restrict__ msg_w2, const float* __restrict__ msg_b2) {
    __shared__ __align__(16) float sW2[1024];
    __shared__ float sB2[32];

    int tid = threadIdx.x;
    for (int k = tid; k < 1024; k += 128) sW2[k] = msg_w2[k];
    if (tid < 32) sB2[tid] = msg_b2[tid];
    __syncthreads();

    int sub = tid & 3;
    int c0 = sub * 8;
    int e0 = blockIdx.x * 64 + (tid >> 2) * 2;

    int2 ip = *(const int2*)&ei[e0];
    int2 jp = *(const int2*)&ei[E_EDGES + e0];
    int iA = ip.x, iB = ip.y;
    int jA = jp.x, jB = jp.y;

    // hoisted gathers: pos, table (nearest row), gate, a/b — maximize MLP
    float4 piA = g_pos4[iA], pjA = g_pos4[jA];
    float4 piB = g_pos4[iB], pjB = g_pos4[jB];
    float dxA = piA.x - pjA.x, dyA = piA.y - pjA.y, dzA = piA.z - pjA.z;
    float dxB = piB.x - pjB.x, dyB = piB.y - pjB.y, dzB = piB.z - pjB.z;
    float distA = sqrtf(dxA * dxA + dyA * dyA + dzA * dzA);
    float distB = sqrtf(dxB * dxB + dyB * dyB + dzB * dzB);

    float uA = fminf(distA, D_CUT) * ((float)(TAB - 1) / D_CUT);
    float uB = fminf(distB, D_CUT) * ((float)(TAB - 1) / D_CUT);
    int i0A = min((int)(uA + 0.5f), TAB - 1);
    int i0B = min((int)(uB + 0.5f), TAB - 1);

    const float4* tAp = (const float4*)&g_tab[i0A * 32 + c0];
    const float4* tBp = (const float4*)&g_tab[i0B * 32 + c0];
    const float4* gAp = (const float4*)&g_gate[jA * 32 + c0];
    const float4* gBp = (const float4*)&g_gate[jB * 32 + c0];

    float egA[8], egB[8];
    {
        float4 t0 = tAp[0], t1 = tAp[1];
        float4 g0 = gAp[0], g1 = gAp[1];
        egA[0] = t0.x * g0.x; egA[1] = t0.y * g0.y;
        egA[2] = t0.z * g0.z; egA[3] = t0.w * g0.w;
        egA[4] = t1.x * g1.x; egA[5] = t1.y * g1.y;
        egA[6] = t1.z * g1.z; egA[7] = t1.w * g1.w;
    }
    {
        float4 t0 = tBp[0], t1 = tBp[1];
        float4 g0 = gBp[0], g1 = gBp[1];
        egB[0] = t0.x * g0.x; egB[1] = t0.y * g0.y;
        egB[2] = t0.z * g0.z; egB[3] = t0.w * g0.w;
        egB[4] = t1.x * g1.x; egB[5] = t1.y * g1.y;
        egB[6] = t1.z * g1.z; egB[7] = t1.w * g1.w;
    }

    float hA[8], hB[8];
    {
        const float4* ap = (const float4*)&g_a[iA * 32 + c0];
        const float4* bp = (const float4*)&g_b[jA * 32 + c0];
        float4 a0 = ap[0], a1 = ap[1], b0 = bp[0], b1 = bp[1];
        hA[0] = siluf(a0.x + b0.x); hA[1] = siluf(a0.y + b0.y);
        hA[2] = siluf(a0.z + b0.z); hA[3] = siluf(a0.w + b0.w);
        hA[4] = siluf(a1.x + b1.x); hA[5] = siluf(a1.y + b1.y);
        hA[6] = siluf(a1.z + b1.z); hA[7] = siluf(a1.w + b1.w);
    }
    {
        const float4* ap = (const float4*)&g_a[iB * 32 + c0];
        const float4* bp = (const float4*)&g_b[jB * 32 + c0];
        float4 a0 = ap[0], a1 = ap[1], b0 = bp[0], b1 = bp[1];
        hB[0] = siluf(a0.x + b0.x); hB[1] = siluf(a0.y + b0.y);
        hB[2] = siluf(a0.z + b0.z); hB[3] = siluf(a0.w + b0.w);
        hB[4] = siluf(a1.x + b1.x); hB[5] = siluf(a1.y + b1.y);
        hB[6] = siluf(a1.z + b1.z); hB[7] = siluf(a1.w + b1.w);
    }

    u64 mmA[4], mmB[4];
    #pragma unroll
    for (int p = 0; p < 4; p++) {
        u64 bb = pack2(sB2[c0 + 2 * p], sB2[c0 + 2 * p + 1]);
        mmA[p] = bb; mmB[p] = bb;
    }
    MV32X2(mmA, mmB, hA, hB, sW2, c0);

    float mA[8], mB[8];
    {
        float t0, t1;
        unpack2(mmA[0], t0, t1); mA[0] = siluf(t0) * egA[0]; mA[1] = siluf(t1) * egA[1];
        unpack2(mmA[1], t0, t1); mA[2] = siluf(t0) * egA[2]; mA[3] = siluf(t1) * egA[3];
        unpack2(mmA[2], t0, t1); mA[4] = siluf(t0) * egA[4]; mA[5] = siluf(t1) * egA[5];
        unpack2(mmA[3], t0, t1); mA[6] = siluf(t0) * egA[6]; mA[7] = siluf(t1) * egA[7];
        unpack2(mmB[0], t0, t1); mB[0] = siluf(t0) * egB[0]; mB[1] = siluf(t1) * egB[1];
        unpack2(mmB[1], t0, t1); mB[2] = siluf(t0) * egB[2]; mB[3] = siluf(t1) * egB[3];
        unpack2(mmB[2], t0, t1); mB[4] = siluf(t0) * egB[4]; mB[5] = siluf(t1) * egB[5];
        unpack2(mmB[3], t0, t1); mB[6] = siluf(t0) * egB[6]; mB[7] = siluf(t1) * egB[7];
    }

    // coalesced store of m for the coord pass
    float4* omA = (float4*)&g_m[e0 * 32 + c0];
    omA[0] = make_float4(mA[0], mA[1], mA[2], mA[3]);
    omA[1] = make_float4(mA[4], mA[5], mA[6], mA[7]);
    float4* omB = (float4*)&g_m[(e0 + 1) * 32 + c0];
    omB[0] = make_float4(mB[0], mB[1], mB[2], mB[3]);
    omB[1] = make_float4(mB[4], mB[5], mB[6], mB[7]);

    // m scatter
    float* maccA = &g_macc[jA * 32 + c0];
    red_v4(maccA,     mA[0], mA[1], mA[2], mA[3]);
    red_v4(maccA + 4, mA[4], mA[5], mA[6], mA[7]);
    float* maccB = &g_macc[jB * 32 + c0];
    red_v4(maccB,     mB[0], mB[1], mB[2], mB[3]);
    red_v4(maccB + 4, mB[4], mB[5], mB[6], mB[7]);

    if (sub == 0) {
        g_dv[e0]     = make_float4(dxA, dyA, dzA, 0.0f);
        g_dv[e0 + 1] = make_float4(dxB, dyB, dzB, 0.0f);
    }
}

// ---------------- K3b: coord kernel (coalesced m -> MV2 -> s -> scatter) ----
__global__ void __launch_bounds__(128) k_edge2(
        const int* __restrict__ ei,
        const float* __restrict__ coord_w1, const float* __restrict__ coord_b1,
        const float* __restrict__ coord_w2, const float* __restrict__ coord_b2) {
    __shared__ __align__(16) float sC1[1024];
    __shared__ float sC2[32], sCB1[32];
    __shared__ float sCB2;

    int tid = threadIdx.x;
    for (int k = tid; k < 1024; k += 128) sC1[k] = coord_w1[k];
    if (tid < 32) {
        sC2[tid]  = coord_w2[tid];
        sCB1[tid] = coord_b1[tid];
    }
    if (tid == 0) sCB2 = coord_b2[0];
    __syncthreads();

    int sub = tid & 3;
    int c0 = sub * 8;
    int e0 = blockIdx.x * 64 + (tid >> 2) * 2;

    // coalesced m loads
    float mA[8], mB[8];
    {
        const float4* mp = (const float4*)&g_m[e0 * 32 + c0];
        float4 m0 = mp[0], m1 = mp[1];
        mA[0] = m0.x; mA[1] = m0.y; mA[2] = m0.z; mA[3] = m0.w;
        mA[4] = m1.x; mA[5] = m1.y; mA[6] = m1.z; mA[7] = m1.w;
    }
    {
        const float4* mp = (const float4*)&g_m[(e0 + 1) * 32 + c0];
        float4 m0 = mp[0], m1 = mp[1];
        mB[0] = m0.x; mB[1] = m0.y; mB[2] = m0.z; mB[3] = m0.w;
        mB[4] = m1.x; mB[5] = m1.y; mB[6] = m1.z; mB[7] = m1.w;
    }

    u64 stA[4], stB[4];
    #pragma unroll
    for (int p = 0; p < 4; p++) {
        u64 bb = pack2(sCB1[c0 + 2 * p], sCB1[c0 + 2 * p + 1]);
        stA[p] = bb; stB[p] = bb;
    }
    MV32X2(stA, stB, mA, mB, sC1, c0);

    float spA = 0.0f, spB = 0.0f;
    #pragma unroll
    for (int p = 0; p < 4; p++) {
        float t0, t1;
        float w0 = sC2[c0 + 2 * p], w1 = sC2[c0 + 2 * p + 1];
        unpack2(stA[p], t0, t1);
        spA += siluf(t0) * w0 + siluf(t1) * w1;
        unpack2(stB[p], t0, t1);
        spB += siluf(t0) * w0 + siluf(t1) * w1;
    }
    spA += __shfl_xor_sync(0xffffffffu, spA, 1);
    spA += __shfl_xor_sync(0xffffffffu, spA, 2);
    spB += __shfl_xor_sync(0xffffffffu, spB, 1);
    spB += __shfl_xor_sync(0xffffffffu, spB, 2);
    float sA = spA + sCB2;
    float sB = spB + sCB2;

    if (sub == 0) {
        int2 jp = *(const int2*)&ei[E_EDGES + e0];
        float4 dvA = g_dv[e0];
        float4 dvB = g_dv[e0 + 1];
        red_v4(&g_pacc[jp.x * 4], dvA.x * sA, dvA.y * sA, dvA.z * sA, 1.0f);
        red_v4(&g_pacc[jp.y * 4], dvB.x * sB, dvB.y * sB, dvB.z * sB, 1.0f);
    }
}

// ---------------- K4: combine + outputs, NE=2 nodes per 4-lane group --------
__global__ void __launch_bounds__(128) k_final(
        const float* __restrict__ pos,
        const float* __restrict__ comb_w1, const float* __restrict__ cb1,
        const float* __restrict__ comb_w2, const float* __restrict__ cb2,
        float* __restrict__ outx, float* __restrict__ outp) {
    __shared__ __align__(16) float sW1[64 * 32];
    __shared__ __align__(16) float sW2[32 * 32];
    int tid = threadIdx.x;
    for (int k = tid; k < 2048; k += 128) sW1[k] = comb_w1[k];
    for (int k = tid; k < 1024; k += 128) sW2[k] = comb_w2[k];
    __syncthreads();

    int sub = tid & 3;
    int c0 = sub * 8;
    int n0 = blockIdx.x * 64 + (tid >> 2) * 2;
    if (n0 >= N_NODES) return;   // warp-uniform
    int n1 = n0 + 1;

    float invA[16], invB[16];
    {
        const float* src = (sub < 2) ? &g_xm[n0 * 32] : &g_macc[n0 * 32];
        const float4* ip = (const float4*)&src[(sub & 1) * 16];
        float4 i0 = ip[0], i1 = ip[1], i2 = ip[2], i3 = ip[3];
        invA[0] = i0.x; invA[1] = i0.y; invA[2] = i0.z; invA[3] = i0.w;
        invA[4] = i1.x; invA[5] = i1.y; invA[6] = i1.z; invA[7] = i1.w;
        invA[8] = i2.x; invA[9] = i2.y; invA[10] = i2.z; invA[11] = i2.w;
        invA[12] = i3.x; invA[13] = i3.y; invA[14] = i3.z; invA[15] = i3.w;
    }
    {
        const float* src = (sub < 2) ? &g_xm[n1 * 32] : &g_macc[n1 * 32];
        const float4* ip = (const float4*)&src[(sub & 1) * 16];
        float4 i0 = ip[0], i1 = ip[1], i2 = ip[2], i3 = ip[3];
        invB[0] = i0.x; invB[1] = i0.y; invB[2] = i0.z; invB[3] = i0.w;
        invB[4] = i1.x; invB[5] = i1.y; invB[6] = i1.z; invB[7] = i1.w;
        invB[8] = i2.x; invB[9] = i2.y; invB[10] = i2.z; invB[11] = i2.w;
        invB[12] = i3.x; invB[13] = i3.y; invB[14] = i3.z; invB[15] = i3.w;
    }

    u64 accA[4], accB[4];
    #pragma unroll
    for (int p = 0; p < 4; p++) {
        u64 bb = pack2(cb1[c0 + 2 * p], cb1[c0 + 2 * p + 1]);
        accA[p] = bb; accB[p] = bb;
    }
    #pragma unroll
    for (int kk = 0; kk < 64; kk++) {
        float vA = __shfl_sync(0xffffffffu, invA[kk & 15], kk >> 4, 4);
        float vB = __shfl_sync(0xffffffffu, invB[kk & 15], kk >> 4, 4);
        u64 vvA = pack2(vA, vA);
        u64 vvB = pack2(vB, vB);
        const ulonglong2* wp = (const ulonglong2*)&sW1[kk * 32 + c0];
        ulonglong2 w0 = wp[0], w1 = wp[1];
        ffma2(accA[0], w0.x, vvA); ffma2(accA[1], w0.y, vvA);
        ffma2(accA[2], w1.x, vvA); ffma2(accA[3], w1.y, vvA);
        ffma2(accB[0], w0.x, vvB); ffma2(accB[1], w0.y, vvB);
        ffma2(accB[2], w1.x, vvB); ffma2(accB[3], w1.y, vvB);
    }
    float hhA[8], hhB[8];
    {
        float t0, t1;
        unpack2(accA[0], t0, t1); hhA[0] = siluf(t0); hhA[1] = siluf(t1);
        unpack2(accA[1], t0, t1); hhA[2] = siluf(t0); hhA[3] = siluf(t1);
        unpack2(accA[2], t0, t1); hhA[4] = siluf(t0); hhA[5] = siluf(t1);
        unpack2(accA[3], t0, t1); hhA[6] = siluf(t0); hhA[7] = siluf(t1);
        unpack2(accB[0], t0, t1); hhB[0] = siluf(t0); hhB[1] = siluf(t1);
        unpack2(accB[1], t0, t1); hhB[2] = siluf(t0); hhB[3] = siluf(t1);
        unpack2(accB[2], t0, t1); hhB[4] = siluf(t0); hhB[5] = siluf(t1);
        unpack2(accB[3], t0, t1); hhB[6] = siluf(t0); hhB[7] = siluf(t1);
    }

    u64 a2A[4], a2B[4];
    #pragma unroll
    for (int p = 0; p < 4; p++) {
        u64 bb = pack2(cb2[c0 + 2 * p], cb2[c0 + 2 * p + 1]);
        a2A[p] = bb; a2B[p] = bb;
    }
    #pragma unroll
    for (int kk = 0; kk < 32; kk++) {
        float vA = __shfl_sync(0xffffffffu, hhA[kk & 7], kk >> 3, 4);
        float vB = __shfl_sync(0xffffffffu, hhB[kk & 7], kk >> 3, 4);
        u64 vvA = pack2(vA, vA);
        u64 vvB = pack2(vB, vB);
        const ulonglong2* wp = (const ulonglong2*)&sW2[kk * 32 + c0];
        ulonglong2 w0 = wp[0], w1 = wp[1];
        ffma2(a2A[0], w0.x, vvA); ffma2(a2A[1], w0.y, vvA);
        ffma2(a2A[2], w1.x, vvA); ffma2(a2A[3], w1.y, vvA);
        ffma2(a2B[0], w0.x, vvB); ffma2(a2B[1], w0.y, vvB);
        ffma2(a2B[2], w1.x, vvB); ffma2(a2B[3], w1.y, vvB);
    }

    {
        float cc[8];
        float t0, t1;
        unpack2(a2A[0], t0, t1); cc[0] = t0; cc[1] = t1;
        unpack2(a2A[1], t0, t1); cc[2] = t0; cc[3] = t1;
        unpack2(a2A[2], t0, t1); cc[4] = t0; cc[5] = t1;
        unpack2(a2A[3], t0, t1); cc[6] = t0; cc[7] = t1;
        const float4* xmp = (const float4*)&g_xm[n0 * 32 + c0];
        float4 xm0 = xmp[0], xm1 = xmp[1];
        float4 o0, o1;
        o0.x = siluf(xm0.x + cc[0]); o0.y = siluf(xm0.y + cc[1]);
        o0.z = siluf(xm0.z + cc[2]); o0.w = siluf(xm0.w + cc[3]);
        o1.x = siluf(xm1.x + cc[4]); o1.y = siluf(xm1.y + cc[5]);
        o1.z = siluf(xm1.z + cc[6]); o1.w = siluf(xm1.w + cc[7]);
        float4* op = (float4*)&outx[n0 * 32 + c0];
        op[0] = o0; op[1] = o1;
    }
    {
        float cc[8];
        float t0, t1;
        unpack2(a2B[0], t0, t1); cc[0] = t0; cc[1] = t1;
        unpack2(a2B[1], t0, t1); cc[2] = t0; cc[3] = t1;
        unpack2(a2B[2], t0, t1); cc[4] = t0; cc[5] = t1;
        unpack2(a2B[3], t0, t1); cc[6] = t0; cc[7] = t1;
        const float4* xmp = (const float4*)&g_xm[n1 * 32 + c0];
        float4 xm0 = xmp[0], xm1 = xmp[1];
        float4 o0, o1;
        o0.x = siluf(xm0.x + cc[0]); o0.y = siluf(xm0.y + cc[1]);
        o0.z = siluf(xm0.z + cc[2]); o0.w = siluf(xm0.w + cc[3]);
        o1.x = siluf(xm1.x + cc[4]); o1.y = siluf(xm1.y + cc[5]);
        o1.z = siluf(xm1.z + cc[6]); o1.w = siluf(xm1.w + cc[7]);
        float4* op = (float4*)&outx[n1 * 32 + c0];
        op[0] = o0; op[1] = o1;
    }

    if (sub == 0) {
        float4 pa = *(const float4*)&g_pacc[n0 * 4];
        float ic = 1.0f / fmaxf(pa.w, 1.0f);
        outp[n0 * 3 + 0] = pos[n0 * 3 + 0] + pa.x * ic;
        outp[n0 * 3 + 1] = pos[n0 * 3 + 1] + pa.y * ic;
        outp[n0 * 3 + 2] = pos[n0 * 3 + 2] + pa.z * ic;
        float4 pb = *(const float4*)&g_pacc[n1 * 4];
        float ic2 = 1.0f / fmaxf(pb.w, 1.0f);
        outp[n1 * 3 + 0] = pos[n1 * 3 + 0] + pb.x * ic2;
        outp[n1 * 3 + 1] = pos[n1 * 3 + 1] + pb.y * ic2;
        outp[n1 * 3 + 2] = pos[n1 * 3 + 2] + pb.z * ic2;
    }
}

// ---------------- launch ----------------
extern "C" void kernel_launch(void* const* d_in, const int* in_sizes, int n_in,
                              void* d_out, int out_size) {
    const float* x        = (const float*)d_in[0];
    const int*   ei       = (const int*)d_in[1];
    const float* pos      = (const float*)d_in[2];
    const float* time     = (const float*)d_in[3];
    const int*   batch    = (const int*)d_in[4];
    const float* means    = (const float*)d_in[5];
    const float* betas    = (const float*)d_in[6];
    const float* w_dist   = (const float*)d_in[7];
    const float* msg_w1   = (const float*)d_in[8];
    const float* msg_b1   = (const float*)d_in[9];
    const float* msg_w2   = (const float*)d_in[10];
    const float* msg_b2   = (const float*)d_in[11];
    const float* gate_w   = (const float*)d_in[12];
    const float* gate_b   = (const float*)d_in[13];
    const float* time_w1  = (const float*)d_in[14];
    const float* time_b1  = (const float*)d_in[15];
    const float* time_w2  = (const float*)d_in[16];
    const float* time_b2  = (const float*)d_in[17];
    const float* comb_w1  = (const float*)d_in[18];
    const float* comb_b1  = (const float*)d_in[19];
    const float* comb_w2  = (const float*)d_in[20];
    const float* comb_b2  = (const float*)d_in[21];
    const float* coord_w1 = (const float*)d_in[22];
    const float* coord_b1 = (const float*)d_in[23];
    const float* coord_w2 = (const float*)d_in[24];
    const float* coord_b2 = (const float*)d_in[25];

    float* outx = (float*)d_out;
    float* outp = (float*)d_out + N_NODES * 32;

    k_time<<<G_GRAPHS / 4 + TAB / 8, 256>>>(time, time_w1, time_b1, time_w2, time_b2,
                                            means, betas, w_dist);
    k_node<<<NODE_BLOCKS, 128>>>(x, batch, pos, msg_w1, msg_b1, gate_w, gate_b);
    k_edge1<<<E_EDGES / 64, 128>>>(ei, msg_w2, msg_b2);
    k_edge2<<<E_EDGES / 64, 128>>>(ei, coord_w1, coord_b1, coord_w2, coord_b2);
    k_final<<<NODE_BLOCKS, 128>>>(pos, comb_w1, comb_b1, comb_w2, comb_b2,
                                  outx, outp);
}

// round 11
// speedup vs baseline: 1.2300x; 1.2300x over previous
#include <cuda_runtime.h>
#include <math.h>

#define N_NODES 100000
#define E_EDGES 800000
#define G_GRAPHS 512
#define HID 32
#define D_CUT 5.0f
#define TAB 8192
#define NODE_BLOCKS 1563   // ceil(100000/64)

typedef unsigned long long u64;

// ---------------- scratch (static, no allocation) ----------------
__device__ __align__(16) float g_ss[G_GRAPHS * 64];
__device__ __align__(16) float g_xm[N_NODES * 32];
__device__ __align__(16) float g_a[N_NODES * 32];
__device__ __align__(16) float g_b[N_NODES * 32];
__device__ __align__(16) float g_gate[N_NODES * 32];
__device__ __align__(16) float g_macc[N_NODES * 32];
__device__ __align__(16) float g_pacc[N_NODES * 4];
__device__ __align__(16) float4 g_pos4[N_NODES];
__device__ __align__(16) float g_tab[TAB * 32];

__device__ __forceinline__ float siluf(float v) { return v / (1.0f + __expf(-v)); }
__device__ __forceinline__ float sigmf(float v) { return 1.0f / (1.0f + __expf(-v)); }

__device__ __forceinline__ void red_v4(float* p, float a, float b, float c, float d) {
    asm volatile("red.global.add.v4.f32 [%0], {%1,%2,%3,%4};"
                 :: "l"(p), "f"(a), "f"(b), "f"(c), "f"(d) : "memory");
}

__device__ __forceinline__ u64 pack2(float lo, float hi) {
    u64 r; asm("mov.b64 %0, {%1, %2};" : "=l"(r) : "f"(lo), "f"(hi)); return r;
}
__device__ __forceinline__ void unpack2(u64 v, float& lo, float& hi) {
    asm("mov.b64 {%0, %1}, %2;" : "=f"(lo), "=f"(hi) : "l"(v));
}
__device__ __forceinline__ void ffma2(u64& d, u64 a, u64 b) {
    asm("fma.rn.f32x2 %0, %1, %2, %0;" : "+l"(d) : "l"(a), "l"(b));
}

// ---------------- K1: time MLP + dist_emb table (fused) ----------------
__global__ void __launch_bounds__(256) k_time(
        const float* __restrict__ time,
        const float* __restrict__ w1, const float* __restrict__ b1,
        const float* __restrict__ w2, const float* __restrict__ b2,
        const float* __restrict__ means, const float* __restrict__ betas,
        const float* __restrict__ w_dist) {
    int tid = threadIdx.x;
    if (blockIdx.x >= G_GRAPHS / 4) {
        __shared__ float sW[1024];
        __shared__ float sMu[32], sBeta[32];
        for (int k = tid; k < 1024; k += 256) sW[k] = w_dist[k];
        if (tid < 32) { sMu[tid] = means[tid]; sBeta[tid] = betas[tid]; }
        __syncthreads();
        int r = (blockIdx.x - G_GRAPHS / 4) * 8 + (tid >> 5);
        int c = tid & 31;
        float d = (float)r * (D_CUT / (float)(TAB - 1));
        float cutoff = 0.5f * (__cosf(d * (3.14159265358979f / D_CUT)) + 1.0f);
        float ed = __expf(-d);
        float acc = 0.0f;
        #pragma unroll 8
        for (int k = 0; k < 32; k++) {
            float t = ed - sMu[k];
            acc += __expf(-sBeta[k] * t * t) * sW[k * 32 + c];
        }
        g_tab[r * 32 + c] = cutoff * acc;
        return;
    }
    __shared__ float trow[4][128];
    __shared__ float hid[4][64];
    int gsub = tid >> 6;
    int t = tid & 63;
    int g = blockIdx.x * 4 + gsub;
    trow[gsub][t]      = time[g * 128 + t];
    trow[gsub][t + 64] = time[g * 128 + 64 + t];
    __syncthreads();
    float acc = b1[t];
    #pragma unroll 8
    for (int k = 0; k < 128; k++) acc += trow[gsub][k] * w1[k * 64 + t];
    hid[gsub][t] = siluf(acc);
    __syncthreads();
    float acc2 = b2[t];
    #pragma unroll 8
    for (int k = 0; k < 64; k++) acc2 += hid[gsub][k] * w2[k * 64 + t];
    g_ss[g * 64 + t] = acc2;
}

// ---------------- K2: per-node precompute, NE=2 nodes per 4-lane group ------
__global__ void __launch_bounds__(128) k_node(
        const float* __restrict__ x, const int* __restrict__ batch,
        const float* __restrict__ pos,
        const float* __restrict__ msg_w1, const float* __restrict__ msg_b1,
        const float* __restrict__ gate_w, const float* __restrict__ gate_b) {
    __shared__ __align__(16) float sW1[64 * 32];
    __shared__ __align__(16) float sWg[32 * 32];
    int tid = threadIdx.x;
    for (int k = tid; k < 2048; k += 128) sW1[k] = msg_w1[k];
    for (int k = tid; k < 1024; k += 128) sWg[k] = gate_w[k];
    __syncthreads();

    int sub = tid & 3;
    int c0 = sub * 8;
    int n0 = blockIdx.x * 64 + (tid >> 2) * 2;
    if (n0 >= N_NODES) return;   // warp-uniform: 16 nodes/warp, 16 | 100000
    int n1 = n0 + 1;

    float xmA[8], xmB[8];
    {
        int bn = batch[n0];
        const float4* scp = (const float4*)&g_ss[bn * 64 + c0];
        const float4* shp = (const float4*)&g_ss[bn * 64 + 32 + c0];
        const float4* xp  = (const float4*)&x[n0 * 32 + c0];
        float4 sc0 = scp[0], sc1 = scp[1];
        float4 sh0 = shp[0], sh1 = shp[1];
        float4 x0 = xp[0], x1 = xp[1];
        xmA[0] = siluf(x0.x * (1.0f + sc0.x) + sh0.x);
        xmA[1] = siluf(x0.y * (1.0f + sc0.y) + sh0.y);
        xmA[2] = siluf(x0.z * (1.0f + sc0.z) + sh0.z);
        xmA[3] = siluf(x0.w * (1.0f + sc0.w) + sh0.w);
        xmA[4] = siluf(x1.x * (1.0f + sc1.x) + sh1.x);
        xmA[5] = siluf(x1.y * (1.0f + sc1.y) + sh1.y);
        xmA[6] = siluf(x1.z * (1.0f + sc1.z) + sh1.z);
        xmA[7] = siluf(x1.w * (1.0f + sc1.w) + sh1.w);
    }
    {
        int bn = batch[n1];
        const float4* scp = (const float4*)&g_ss[bn * 64 + c0];
        const float4* shp = (const float4*)&g_ss[bn * 64 + 32 + c0];
        const float4* xp  = (const float4*)&x[n1 * 32 + c0];
        float4 sc0 = scp[0], sc1 = scp[1];
        float4 sh0 = shp[0], sh1 = shp[1];
        float4 x0 = xp[0], x1 = xp[1];
        xmB[0] = siluf(x0.x * (1.0f + sc0.x) + sh0.x);
        xmB[1] = siluf(x0.y * (1.0f + sc0.y) + sh0.y);
        xmB[2] = siluf(x0.z * (1.0f + sc0.z) + sh0.z);
        xmB[3] = siluf(x0.w * (1.0f + sc0.w) + sh0.w);
        xmB[4] = siluf(x1.x * (1.0f + sc1.x) + sh1.x);
        xmB[5] = siluf(x1.y * (1.0f + sc1.y) + sh1.y);
        xmB[6] = siluf(x1.z * (1.0f + sc1.z) + sh1.z);
        xmB[7] = siluf(x1.w * (1.0f + sc1.w) + sh1.w);
    }

    u64 aA[4], bA[4], gA[4], aB[4], bB[4], gB[4];
    #pragma unroll
    for (int p = 0; p < 4; p++) {
        u64 mb = pack2(msg_b1[c0 + 2 * p], msg_b1[c0 + 2 * p + 1]);
        u64 gb = pack2(gate_b[c0 + 2 * p], gate_b[c0 + 2 * p + 1]);
        aA[p] = mb; aB[p] = mb;
        bA[p] = 0ULL; bB[p] = 0ULL;
        gA[p] = gb; gB[p] = gb;
    }
    #pragma unroll
    for (int kk = 0; kk < 32; kk++) {
        float vA = __shfl_sync(0xffffffffu, xmA[kk & 7], kk >> 3, 4);
        float vB = __shfl_sync(0xffffffffu, xmB[kk & 7], kk >> 3, 4);
        u64 vvA = pack2(vA, vA);
        u64 vvB = pack2(vB, vB);
        const ulonglong2* wa = (const ulonglong2*)&sW1[kk * 32 + c0];
        const ulonglong2* wb = (const ulonglong2*)&sW1[(32 + kk) * 32 + c0];
        const ulonglong2* wg = (const ulonglong2*)&sWg[kk * 32 + c0];
        ulonglong2 wa0 = wa[0], wa1 = wa[1];
        ulonglong2 wb0 = wb[0], wb1 = wb[1];
        ulonglong2 wg0 = wg[0], wg1 = wg[1];
        ffma2(aA[0], wa0.x, vvA); ffma2(aA[1], wa0.y, vvA);
        ffma2(aA[2], wa1.x, vvA); ffma2(aA[3], wa1.y, vvA);
        ffma2(aB[0], wa0.x, vvB); ffma2(aB[1], wa0.y, vvB);
        ffma2(aB[2], wa1.x, vvB); ffma2(aB[3], wa1.y, vvB);
        ffma2(bA[0], wb0.x, vvA); ffma2(bA[1], wb0.y, vvA);
        ffma2(bA[2], wb1.x, vvA); ffma2(bA[3], wb1.y, vvA);
        ffma2(bB[0], wb0.x, vvB); ffma2(bB[1], wb0.y, vvB);
        ffma2(bB[2], wb1.x, vvB); ffma2(bB[3], wb1.y, vvB);
        ffma2(gA[0], wg0.x, vvA); ffma2(gA[1], wg0.y, vvA);
        ffma2(gA[2], wg1.x, vvA); ffma2(gA[3], wg1.y, vvA);
        ffma2(gB[0], wg0.x, vvB); ffma2(gB[1], wg0.y, vvB);
        ffma2(gB[2], wg1.x, vvB); ffma2(gB[3], wg1.y, vvB);
    }

    {
        float4* oxm = (float4*)&g_xm[n0 * 32 + c0];
        oxm[0] = make_float4(xmA[0], xmA[1], xmA[2], xmA[3]);
        oxm[1] = make_float4(xmA[4], xmA[5], xmA[6], xmA[7]);
        ulonglong2* oa = (ulonglong2*)&g_a[n0 * 32 + c0];
        oa[0] = make_ulonglong2(aA[0], aA[1]); oa[1] = make_ulonglong2(aA[2], aA[3]);
        ulonglong2* ob = (ulonglong2*)&g_b[n0 * 32 + c0];
        ob[0] = make_ulonglong2(bA[0], bA[1]); ob[1] = make_ulonglong2(bA[2], bA[3]);
        float gg[8];
        unpack2(gA[0], gg[0], gg[1]); unpack2(gA[1], gg[2], gg[3]);
        unpack2(gA[2], gg[4], gg[5]); unpack2(gA[3], gg[6], gg[7]);
        float4* og = (float4*)&g_gate[n0 * 32 + c0];
        og[0] = make_float4(sigmf(gg[0]), sigmf(gg[1]), sigmf(gg[2]), sigmf(gg[3]));
        og[1] = make_float4(sigmf(gg[4]), sigmf(gg[5]), sigmf(gg[6]), sigmf(gg[7]));
    }
    {
        float4* oxm = (float4*)&g_xm[n1 * 32 + c0];
        oxm[0] = make_float4(xmB[0], xmB[1], xmB[2], xmB[3]);
        oxm[1] = make_float4(xmB[4], xmB[5], xmB[6], xmB[7]);
        ulonglong2* oa = (ulonglong2*)&g_a[n1 * 32 + c0];
        oa[0] = make_ulonglong2(aB[0], aB[1]); oa[1] = make_ulonglong2(aB[2], aB[3]);
        ulonglong2* ob = (ulonglong2*)&g_b[n1 * 32 + c0];
        ob[0] = make_ulonglong2(bB[0], bB[1]); ob[1] = make_ulonglong2(bB[2], bB[3]);
        float gg[8];
        unpack2(gB[0], gg[0], gg[1]); unpack2(gB[1], gg[2], gg[3]);
        unpack2(gB[2], gg[4], gg[5]); unpack2(gB[3], gg[6], gg[7]);
        float4* og = (float4*)&g_gate[n1 * 32 + c0];
        og[0] = make_float4(sigmf(gg[0]), sigmf(gg[1]), sigmf(gg[2]), sigmf(gg[3]));
        og[1] = make_float4(sigmf(gg[4]), sigmf(gg[5]), sigmf(gg[6]), sigmf(gg[7]));
    }

    float4 z = make_float4(0.f, 0.f, 0.f, 0.f);
    float4* mzA = (float4*)&g_macc[n0 * 32 + c0];
    mzA[0] = z; mzA[1] = z;
    float4* mzB = (float4*)&g_macc[n1 * 32 + c0];
    mzB[0] = z; mzB[1] = z;
    if (sub == 0) {
        *(float4*)&g_pacc[n0 * 4] = z;
        *(float4*)&g_pacc[n1 * 4] = z;
        g_pos4[n0] = make_float4(pos[n0 * 3], pos[n0 * 3 + 1], pos[n0 * 3 + 2], 0.0f);
        g_pos4[n1] = make_float4(pos[n1 * 3], pos[n1 * 3 + 1], pos[n1 * 3 + 2], 0.0f);
    }
}

// ---------------- K3: edge kernel, 8 lanes/group x NE=4 edges ----------------
// warp = 4 groups of 8 lanes; group handles 4 edges; lane owns 4 channels.
// Per kk: 1 LDS.128 (shared by 4 edges) + 4 shfl + 4 pack + 8 ffma2.
// Weight-LDS bytes per edge halved vs NE=2 layout.
#define MV32X4(aA, aB, aC, aD, iA_, iB_, iC_, iD_, W, c0)                        \
    do {                                                                         \
        _Pragma("unroll")                                                        \
        for (int kk = 0; kk < 32; kk++) {                                        \
            float vA = __shfl_sync(0xffffffffu, iA_[kk & 3], kk >> 2, 8);        \
            float vB = __shfl_sync(0xffffffffu, iB_[kk & 3], kk >> 2, 8);        \
            float vC = __shfl_sync(0xffffffffu, iC_[kk & 3], kk >> 2, 8);        \
            float vD = __shfl_sync(0xffffffffu, iD_[kk & 3], kk >> 2, 8);        \
            u64 vvA = pack2(vA, vA), vvB = pack2(vB, vB);                        \
            u64 vvC = pack2(vC, vC), vvD = pack2(vD, vD);                        \
            ulonglong2 w = *(const ulonglong2*)&W[kk * 32 + c0];                 \
            ffma2(aA[0], w.x, vvA); ffma2(aA[1], w.y, vvA);                      \
            ffma2(aB[0], w.x, vvB); ffma2(aB[1], w.y, vvB);                      \
            ffma2(aC[0], w.x, vvC); ffma2(aC[1], w.y, vvC);                      \
            ffma2(aD[0], w.x, vvD); ffma2(aD[1], w.y, vvD);                      \
        }                                                                        \
    } while (0)

__global__ void __launch_bounds__(128) k_edge(
        const int* __restrict__ ei,
        const float* __restrict__ msg_w2, const float* __restrict__ msg_b2,
        const float* __restrict__ coord_w1, const float* __restrict__ coord_b1,
        const float* __restrict__ coord_w2, const float* __restrict__ coord_b2) {
    __shared__ __align__(16) float sW2[1024];
    __shared__ __align__(16) float sC1[1024];
    __shared__ float sC2[32], sB2[32], sCB1[32];
    __shared__ float sCB2;

    int tid = threadIdx.x;
    for (int k = tid; k < 1024; k += 128) {
        sW2[k] = msg_w2[k];
        sC1[k] = coord_w1[k];
    }
    if (tid < 32) {
        sC2[tid]  = coord_w2[tid];
        sB2[tid]  = msg_b2[tid];
        sCB1[tid] = coord_b1[tid];
    }
    if (tid == 0) sCB2 = coord_b2[0];
    __syncthreads();

    int q = tid & 7;          // channel sub within group
    int c0 = q * 4;
    int e0 = blockIdx.x * 64 + (tid >> 3) * 4;   // E = 800000 = 12500*64

    int4 iv = *(const int4*)&ei[e0];
    int4 jv = *(const int4*)&ei[E_EDGES + e0];

    // per-lane edge assignment for pos/dist: edge (q & 3)
    int eq = q & 3;
    int i_own = (eq & 2) ? ((eq & 1) ? iv.w : iv.z) : ((eq & 1) ? iv.y : iv.x);
    int j_own = (eq & 2) ? ((eq & 1) ? jv.w : jv.z) : ((eq & 1) ? jv.y : jv.x);
    float4 pi = g_pos4[i_own], pj = g_pos4[j_own];
    float dx = pi.x - pj.x, dy = pi.y - pj.y, dz = pi.z - pj.z;
    float dist = sqrtf(dx * dx + dy * dy + dz * dz);
    float u = fminf(dist, D_CUT) * ((float)(TAB - 1) / D_CUT);
    int i0_own = min((int)(u + 0.5f), TAB - 1);

    int i0A = __shfl_sync(0xffffffffu, i0_own, 0, 8);
    int i0B = __shfl_sync(0xffffffffu, i0_own, 1, 8);
    int i0C = __shfl_sync(0xffffffffu, i0_own, 2, 8);
    int i0D = __shfl_sync(0xffffffffu, i0_own, 3, 8);

    // hoisted gathers per edge (1 float4/lane per row)
    float hA[4], egA[4], hB[4], egB[4], hC[4], egC[4], hD[4], egD[4];
    {
        float4 a = *(const float4*)&g_a[iv.x * 32 + c0];
        float4 b = *(const float4*)&g_b[jv.x * 32 + c0];
        float4 t = *(const float4*)&g_tab[i0A * 32 + c0];
        float4 g = *(const float4*)&g_gate[jv.x * 32 + c0];
        hA[0] = siluf(a.x + b.x); hA[1] = siluf(a.y + b.y);
        hA[2] = siluf(a.z + b.z); hA[3] = siluf(a.w + b.w);
        egA[0] = t.x * g.x; egA[1] = t.y * g.y; egA[2] = t.z * g.z; egA[3] = t.w * g.w;
    }
    {
        float4 a = *(const float4*)&g_a[iv.y * 32 + c0];
        float4 b = *(const float4*)&g_b[jv.y * 32 + c0];
        float4 t = *(const float4*)&g_tab[i0B * 32 + c0];
        float4 g = *(const float4*)&g_gate[jv.y * 32 + c0];
        hB[0] = siluf(a.x + b.x); hB[1] = siluf(a.y + b.y);
        hB[2] = siluf(a.z + b.z); hB[3] = siluf(a.w + b.w);
        egB[0] = t.x * g.x; egB[1] = t.y * g.y; egB[2] = t.z * g.z; egB[3] = t.w * g.w;
    }
    {
        float4 a = *(const float4*)&g_a[iv.z * 32 + c0];
        float4 b = *(const float4*)&g_b[jv.z * 32 + c0];
        float4 t = *(const float4*)&g_tab[i0C * 32 + c0];
        float4 g = *(const float4*)&g_gate[jv.z * 32 + c0];
        hC[0] = siluf(a.x + b.x); hC[1] = siluf(a.y + b.y);
        hC[2] = siluf(a.z + b.z); hC[3] = siluf(a.w + b.w);
        egC[0] = t.x * g.x; egC[1] = t.y * g.y; egC[2] = t.z * g.z; egC[3] = t.w * g.w;
    }
    {
        float4 a = *(const float4*)&g_a[iv.w * 32 + c0];
        float4 b = *(const float4*)&g_b[jv.w * 32 + c0];
        float4 t = *(const float4*)&g_tab[i0D * 32 + c0];
        float4 g = *(const float4*)&g_gate[jv.w * 32 + c0];
        hD[0] = siluf(a.x + b.x); hD[1] = siluf(a.y + b.y);
        hD[2] = siluf(a.z + b.z); hD[3] = siluf(a.w + b.w);
        egD[0] = t.x * g.x; egD[1] = t.y * g.y; egD[2] = t.z * g.z; egD[3] = t.w * g.w;
    }

    // MV1: msg_w2
    u64 mmA[2], mmB[2], mmC[2], mmD[2];
    {
        u64 b0 = pack2(sB2[c0], sB2[c0 + 1]);
        u64 b1 = pack2(sB2[c0 + 2], sB2[c0 + 3]);
        mmA[0] = b0; mmA[1] = b1; mmB[0] = b0; mmB[1] = b1;
        mmC[0] = b0; mmC[1] = b1; mmD[0] = b0; mmD[1] = b1;
    }
    MV32X4(mmA, mmB, mmC, mmD, hA, hB, hC, hD, sW2, c0);

    float mA[4], mB[4], mC[4], mD[4];
    {
        float t0, t1;
        unpack2(mmA[0], t0, t1); mA[0] = siluf(t0) * egA[0]; mA[1] = siluf(t1) * egA[1];
        unpack2(mmA[1], t0, t1); mA[2] = siluf(t0) * egA[2]; mA[3] = siluf(t1) * egA[3];
        unpack2(mmB[0], t0, t1); mB[0] = siluf(t0) * egB[0]; mB[1] = siluf(t1) * egB[1];
        unpack2(mmB[1], t0, t1); mB[2] = siluf(t0) * egB[2]; mB[3] = siluf(t1) * egB[3];
        unpack2(mmC[0], t0, t1); mC[0] = siluf(t0) * egC[0]; mC[1] = siluf(t1) * egC[1];
        unpack2(mmC[1], t0, t1); mC[2] = siluf(t0) * egC[2]; mC[3] = siluf(t1) * egC[3];
        unpack2(mmD[0], t0, t1); mD[0] = siluf(t0) * egD[0]; mD[1] = siluf(t1) * egD[1];
        unpack2(mmD[1], t0, t1); mD[2] = siluf(t0) * egD[2]; mD[3] = siluf(t1) * egD[3];
    }

    // m scatter (one red.v4 per edge per lane; 8 lanes cover 32 channels)
    red_v4(&g_macc[jv.x * 32 + c0], mA[0], mA[1], mA[2], mA[3]);
    red_v4(&g_macc[jv.y * 32 + c0], mB[0], mB[1], mB[2], mB[3]);
    red_v4(&g_macc[jv.z * 32 + c0], mC[0], mC[1], mC[2], mC[3]);
    red_v4(&g_macc[jv.w * 32 + c0], mD[0], mD[1], mD[2], mD[3]);

    // MV2: coord_w1
    u64 stA[2], stB[2], stC[2], stD[2];
    {
        u64 b0 = pack2(sCB1[c0], sCB1[c0 + 1]);
        u64 b1 = pack2(sCB1[c0 + 2], sCB1[c0 + 3]);
        stA[0] = b0; stA[1] = b1; stB[0] = b0; stB[1] = b1;
        stC[0] = b0; stC[1] = b1; stD[0] = b0; stD[1] = b1;
    }
    MV32X4(stA, stB, stC, stD, mA, mB, mC, mD, sC1, c0);

    float w0 = sC2[c0], w1 = sC2[c0 + 1], w2 = sC2[c0 + 2], w3 = sC2[c0 + 3];
    float spA, spB, spC, spD;
    {
        float t0, t1, t2, t3;
        unpack2(stA[0], t0, t1); unpack2(stA[1], t2, t3);
        spA = siluf(t0) * w0 + siluf(t1) * w1 + siluf(t2) * w2 + siluf(t3) * w3;
        unpack2(stB[0], t0, t1); unpack2(stB[1], t2, t3);
        spB = siluf(t0) * w0 + siluf(t1) * w1 + siluf(t2) * w2 + siluf(t3) * w3;
        unpack2(stC[0], t0, t1); unpack2(stC[1], t2, t3);
        spC = siluf(t0) * w0 + siluf(t1) * w1 + siluf(t2) * w2 + siluf(t3) * w3;
        unpack2(stD[0], t0, t1); unpack2(stD[1], t2, t3);
        spD = siluf(t0) * w0 + siluf(t1) * w1 + siluf(t2) * w2 + siluf(t3) * w3;
    }
    // reduce over the 8-lane group (xor 1,2,4 stays within 8-aligned groups)
    spA += __shfl_xor_sync(0xffffffffu, spA, 1);
    spA += __shfl_xor_sync(0xffffffffu, spA, 2);
    spA += __shfl_xor_sync(0xffffffffu, spA, 4);
    spB += __shfl_xor_sync(0xffffffffu, spB, 1);
    spB += __shfl_xor_sync(0xffffffffu, spB, 2);
    spB += __shfl_xor_sync(0xffffffffu, spB, 4);
    spC += __shfl_xor_sync(0xffffffffu, spC, 1);
    spC += __shfl_xor_sync(0xffffffffu, spC, 2);
    spC += __shfl_xor_sync(0xffffffffu, spC, 4);
    spD += __shfl_xor_sync(0xffffffffu, spD, 1);
    spD += __shfl_xor_sync(0xffffffffu, spD, 2);
    spD += __shfl_xor_sync(0xffffffffu, spD, 4);

    if (q < 4) {
        float s_own = (q & 2) ? ((q & 1) ? spD : spC) : ((q & 1) ? spB : spA);
        s_own += sCB2;
        red_v4(&g_pacc[j_own * 4], dx * s_own, dy * s_own, dz * s_own, 1.0f);
    }
}

// ---------------- K4: combine + outputs, NE=2 nodes per 4-lane group --------
__global__ void __launch_bounds__(128) k_final(
        const float* __restrict__ pos,
        const float* __restrict__ comb_w1, const float* __restrict__ cb1,
        const float* __restrict__ comb_w2, const float* __restrict__ cb2,
        float* __restrict__ outx, float* __restrict__ outp) {
    __shared__ __align__(16) float sW1[64 * 32];
    __shared__ __align__(16) float sW2[32 * 32];
    int tid = threadIdx.x;
    for (int k = tid; k < 2048; k += 128) sW1[k] = comb_w1[k];
    for (int k = tid; k < 1024; k += 128) sW2[k] = comb_w2[k];
    __syncthreads();

    int sub = tid & 3;
    int c0 = sub * 8;
    int n0 = blockIdx.x * 64 + (tid >> 2) * 2;
    if (n0 >= N_NODES) return;   // warp-uniform
    int n1 = n0 + 1;

    float invA[16], invB[16];
    {
        const float* src = (sub < 2) ? &g_xm[n0 * 32] : &g_macc[n0 * 32];
        const float4* ip = (const float4*)&src[(sub & 1) * 16];
        float4 i0 = ip[0], i1 = ip[1], i2 = ip[2], i3 = ip[3];
        invA[0] = i0.x; invA[1] = i0.y; invA[2] = i0.z; invA[3] = i0.w;
        invA[4] = i1.x; invA[5] = i1.y; invA[6] = i1.z; invA[7] = i1.w;
        invA[8] = i2.x; invA[9] = i2.y; invA[10] = i2.z; invA[11] = i2.w;
        invA[12] = i3.x; invA[13] = i3.y; invA[14] = i3.z; invA[15] = i3.w;
    }
    {
        const float* src = (sub < 2) ? &g_xm[n1 * 32] : &g_macc[n1 * 32];
        const float4* ip = (const float4*)&src[(sub & 1) * 16];
        float4 i0 = ip[0], i1 = ip[1], i2 = ip[2], i3 = ip[3];
        invB[0] = i0.x; invB[1] = i0.y; invB[2] = i0.z; invB[3] = i0.w;
        invB[4] = i1.x; invB[5] = i1.y; invB[6] = i1.z; invB[7] = i1.w;
        invB[8] = i2.x; invB[9] = i2.y; invB[10] = i2.z; invB[11] = i2.w;
        invB[12] = i3.x; invB[13] = i3.y; invB[14] = i3.z; invB[15] = i3.w;
    }

    u64 accA[4], accB[4];
    #pragma unroll
    for (int p = 0; p < 4; p++) {
        u64 bb = pack2(cb1[c0 + 2 * p], cb1[c0 + 2 * p + 1]);
        accA[p] = bb; accB[p] = bb;
    }
    #pragma unroll
    for (int kk = 0; kk < 64; kk++) {
        float vA = __shfl_sync(0xffffffffu, invA[kk & 15], kk >> 4, 4);
        float vB = __shfl_sync(0xffffffffu, invB[kk & 15], kk >> 4, 4);
        u64 vvA = pack2(vA, vA);
        u64 vvB = pack2(vB, vB);
        const ulonglong2* wp = (const ulonglong2*)&sW1[kk * 32 + c0];
        ulonglong2 w0 = wp[0], w1 = wp[1];
        ffma2(accA[0], w0.x, vvA); ffma2(accA[1], w0.y, vvA);
        ffma2(accA[2], w1.x, vvA); ffma2(accA[3], w1.y, vvA);
        ffma2(accB[0], w0.x, vvB); ffma2(accB[1], w0.y, vvB);
        ffma2(accB[2], w1.x, vvB); ffma2(accB[3], w1.y, vvB);
    }
    float hhA[8], hhB[8];
    {
        float t0, t1;
        unpack2(accA[0], t0, t1); hhA[0] = siluf(t0); hhA[1] = siluf(t1);
        unpack2(accA[1], t0, t1); hhA[2] = siluf(t0); hhA[3] = siluf(t1);
        unpack2(accA[2], t0, t1); hhA[4] = siluf(t0); hhA[5] = siluf(t1);
        unpack2(accA[3], t0, t1); hhA[6] = siluf(t0); hhA[7] = siluf(t1);
        unpack2(accB[0], t0, t1); hhB[0] = siluf(t0); hhB[1] = siluf(t1);
        unpack2(accB[1], t0, t1); hhB[2] = siluf(t0); hhB[3] = siluf(t1);
        unpack2(accB[2], t0, t1); hhB[4] = siluf(t0); hhB[5] = siluf(t1);
        unpack2(accB[3], t0, t1); hhB[6] = siluf(t0); hhB[7] = siluf(t1);
    }

    u64 a2A[4], a2B[4];
    #pragma unroll
    for (int p = 0; p < 4; p++) {
        u64 bb = pack2(cb2[c0 + 2 * p], cb2[c0 + 2 * p + 1]);
        a2A[p] = bb; a2B[p] = bb;
    }
    #pragma unroll
    for (int kk = 0; kk < 32; kk++) {
        float vA = __shfl_sync(0xffffffffu, hhA[kk & 7], kk >> 3, 4);
        float vB = __shfl_sync(0xffffffffu, hhB[kk & 7], kk >> 3, 4);
        u64 vvA = pack2(vA, vA);
        u64 vvB = pack2(vB, vB);
        const ulonglong2* wp = (const ulonglong2*)&sW2[kk * 32 + c0];
        ulonglong2 w0 = wp[0], w1 = wp[1];
        ffma2(a2A[0], w0.x, vvA); ffma2(a2A[1], w0.y, vvA);
        ffma2(a2A[2], w1.x, vvA); ffma2(a2A[3], w1.y, vvA);
        ffma2(a2B[0], w0.x, vvB); ffma2(a2B[1], w0.y, vvB);
        ffma2(a2B[2], w1.x, vvB); ffma2(a2B[3], w1.y, vvB);
    }

    {
        float cc[8];
        float t0, t1;
        unpack2(a2A[0], t0, t1); cc[0] = t0; cc[1] = t1;
        unpack2(a2A[1], t0, t1); cc[2] = t0; cc[3] = t1;
        unpack2(a2A[2], t0, t1); cc[4] = t0; cc[5] = t1;
        unpack2(a2A[3], t0, t1); cc[6] = t0; cc[7] = t1;
        const float4* xmp = (const float4*)&g_xm[n0 * 32 + c0];
        float4 xm0 = xmp[0], xm1 = xmp[1];
        float4 o0, o1;
        o0.x = siluf(xm0.x + cc[0]); o0.y = siluf(xm0.y + cc[1]);
        o0.z = siluf(xm0.z + cc[2]); o0.w = siluf(xm0.w + cc[3]);
        o1.x = siluf(xm1.x + cc[4]); o1.y = siluf(xm1.y + cc[5]);
        o1.z = siluf(xm1.z + cc[6]); o1.w = siluf(xm1.w + cc[7]);
        float4* op = (float4*)&outx[n0 * 32 + c0];
        op[0] = o0; op[1] = o1;
    }
    {
        float cc[8];
        float t0, t1;
        unpack2(a2B[0], t0, t1); cc[0] = t0; cc[1] = t1;
        unpack2(a2B[1], t0, t1); cc[2] = t0; cc[3] = t1;
        unpack2(a2B[2], t0, t1); cc[4] = t0; cc[5] = t1;
        unpack2(a2B[3], t0, t1); cc[6] = t0; cc[7] = t1;
        const float4* xmp = (const float4*)&g_xm[n1 * 32 + c0];
        float4 xm0 = xmp[0], xm1 = xmp[1];
        float4 o0, o1;
        o0.x = siluf(xm0.x + cc[0]); o0.y = siluf(xm0.y + cc[1]);
        o0.z = siluf(xm0.z + cc[2]); o0.w = siluf(xm0.w + cc[3]);
        o1.x = siluf(xm1.x + cc[4]); o1.y = siluf(xm1.y + cc[5]);
        o1.z = siluf(xm1.z + cc[6]); o1.w = siluf(xm1.w + cc[7]);
        float4* op = (float4*)&outx[n1 * 32 + c0];
        op[0] = o0; op[1] = o1;
    }

    if (sub == 0) {
        float4 pa = *(const float4*)&g_pacc[n0 * 4];
        float ic = 1.0f / fmaxf(pa.w, 1.0f);
        outp[n0 * 3 + 0] = pos[n0 * 3 + 0] + pa.x * ic;
        outp[n0 * 3 + 1] = pos[n0 * 3 + 1] + pa.y * ic;
        outp[n0 * 3 + 2] = pos[n0 * 3 + 2] + pa.z * ic;
        float4 pb = *(const float4*)&g_pacc[n1 * 4];
        float ic2 = 1.0f / fmaxf(pb.w, 1.0f);
        outp[n1 * 3 + 0] = pos[n1 * 3 + 0] + pb.x * ic2;
        outp[n1 * 3 + 1] = pos[n1 * 3 + 1] + pb.y * ic2;
        outp[n1 * 3 + 2] = pos[n1 * 3 + 2] + pb.z * ic2;
    }
}

// ---------------- launch ----------------
extern "C" void kernel_launch(void* const* d_in, const int* in_sizes, int n_in,
                              void* d_out, int out_size) {
    const float* x        = (const float*)d_in[0];
    const int*   ei       = (const int*)d_in[1];
    const float* pos      = (const float*)d_in[2];
    const float* time     = (const float*)d_in[3];
    const int*   batch    = (const int*)d_in[4];
    const float* means    = (const float*)d_in[5];
    const float* betas    = (const float*)d_in[6];
    const float* w_dist   = (const float*)d_in[7];
    const float* msg_w1   = (const float*)d_in[8];
    const float* msg_b1   = (const float*)d_in[9];
    const float* msg_w2   = (const float*)d_in[10];
    const float* msg_b2   = (const float*)d_in[11];
    const float* gate_w   = (const float*)d_in[12];
    const float* gate_b   = (const float*)d_in[13];
    const float* time_w1  = (const float*)d_in[14];
    const float* time_b1  = (const float*)d_in[15];
    const float* time_w2  = (const float*)d_in[16];
    const float* time_b2  = (const float*)d_in[17];
    const float* comb_w1  = (const float*)d_in[18];
    const float* comb_b1  = (const float*)d_in[19];
    const float* comb_w2  = (const float*)d_in[20];
    const float* comb_b2  = (const float*)d_in[21];
    const float* coord_w1 = (const float*)d_in[22];
    const float* coord_b1 = (const float*)d_in[23];
    const float* coord_w2 = (const float*)d_in[24];
    const float* coord_b2 = (const float*)d_in[25];

    float* outx = (float*)d_out;
    float* outp = (float*)d_out + N_NODES * 32;

    k_time<<<G_GRAPHS / 4 + TAB / 8, 256>>>(time, time_w1, time_b1, time_w2, time_b2,
                                            means, betas, w_dist);
    k_node<<<NODE_BLOCKS, 128>>>(x, batch, pos, msg_w1, msg_b1, gate_w, gate_b);
    k_edge<<<E_EDGES / 64, 128>>>(ei, msg_w2, msg_b2,
                                  coord_w1, coord_b1, coord_w2, coord_b2);
    k_final<<<NODE_BLOCKS, 128>>>(pos, comb_w1, comb_b1, comb_w2, comb_b2,
                                  outx, outp);
}

// round 12
// speedup vs baseline: 1.3227x; 1.0754x over previous
#include <cuda_runtime.h>
#include <math.h>

#define N_NODES 100000
#define E_EDGES 800000
#define G_GRAPHS 512
#define HID 32
#define D_CUT 5.0f
#define TAB 8192
#define NODE_BLOCKS 1563   // ceil(100000/64)

typedef unsigned long long u64;

// ---------------- scratch (static, no allocation) ----------------
__device__ __align__(16) float g_ss[G_GRAPHS * 64];
__device__ __align__(16) float g_xm[N_NODES * 32];
__device__ __align__(16) float g_a[N_NODES * 32];
__device__ __align__(16) float g_b[N_NODES * 32];
__device__ __align__(16) float g_gate[N_NODES * 32];
__device__ __align__(16) float g_macc[N_NODES * 32];
__device__ __align__(16) float g_pacc[N_NODES * 4];
__device__ __align__(16) float4 g_pos4[N_NODES];
__device__ __align__(16) float g_tab[TAB * 32];

__device__ __forceinline__ float siluf(float v) { return v / (1.0f + __expf(-v)); }
__device__ __forceinline__ float sigmf(float v) { return 1.0f / (1.0f + __expf(-v)); }

__device__ __forceinline__ void red_v4(float* p, float a, float b, float c, float d) {
    asm volatile("red.global.add.v4.f32 [%0], {%1,%2,%3,%4};"
                 :: "l"(p), "f"(a), "f"(b), "f"(c), "f"(d) : "memory");
}

__device__ __forceinline__ u64 pack2(float lo, float hi) {
    u64 r; asm("mov.b64 %0, {%1, %2};" : "=l"(r) : "f"(lo), "f"(hi)); return r;
}
__device__ __forceinline__ void unpack2(u64 v, float& lo, float& hi) {
    asm("mov.b64 {%0, %1}, %2;" : "=f"(lo), "=f"(hi) : "l"(v));
}
__device__ __forceinline__ void ffma2(u64& d, u64 a, u64 b) {
    asm("fma.rn.f32x2 %0, %1, %2, %0;" : "+l"(d) : "l"(a), "l"(b));
}

// ---------------- K1: time MLP + dist_emb table (fused) ----------------
__global__ void __launch_bounds__(256) k_time(
        const float* __restrict__ time,
        const float* __restrict__ w1, const float* __restrict__ b1,
        const float* __restrict__ w2, const float* __restrict__ b2,
        const float* __restrict__ means, const float* __restrict__ betas,
        const float* __restrict__ w_dist) {
    int tid = threadIdx.x;
    if (blockIdx.x >= G_GRAPHS / 4) {
        __shared__ float sW[1024];
        __shared__ float sMu[32], sBeta[32];
        for (int k = tid; k < 1024; k += 256) sW[k] = w_dist[k];
        if (tid < 32) { sMu[tid] = means[tid]; sBeta[tid] = betas[tid]; }
        __syncthreads();
        int r = (blockIdx.x - G_GRAPHS / 4) * 8 + (tid >> 5);
        int c = tid & 31;
        float d = (float)r * (D_CUT / (float)(TAB - 1));
        float cutoff = 0.5f * (__cosf(d * (3.14159265358979f / D_CUT)) + 1.0f);
        float ed = __expf(-d);
        float acc = 0.0f;
        #pragma unroll 8
        for (int k = 0; k < 32; k++) {
            float t = ed - sMu[k];
            acc += __expf(-sBeta[k] * t * t) * sW[k * 32 + c];
        }
        g_tab[r * 32 + c] = cutoff * acc;
        return;
    }
    __shared__ float trow[4][128];
    __shared__ float hid[4][64];
    int gsub = tid >> 6;
    int t = tid & 63;
    int g = blockIdx.x * 4 + gsub;
    trow[gsub][t]      = time[g * 128 + t];
    trow[gsub][t + 64] = time[g * 128 + 64 + t];
    __syncthreads();
    float acc = b1[t];
    #pragma unroll 8
    for (int k = 0; k < 128; k++) acc += trow[gsub][k] * w1[k * 64 + t];
    hid[gsub][t] = siluf(acc);
    __syncthreads();
    float acc2 = b2[t];
    #pragma unroll 8
    for (int k = 0; k < 64; k++) acc2 += hid[gsub][k] * w2[k * 64 + t];
    g_ss[g * 64 + t] = acc2;
}

// ---------------- K2: per-node precompute, 8 lanes x NE=4 nodes -------------
// group handles nodes n0..n0+3; lane owns 4 channels. Per kk: 3 LDS.128
// (shared by 4 nodes AND shared input broadcast across 3 matvecs) + 4 shfl
// + 24 ffma2.
__global__ void __launch_bounds__(128) k_node(
        const float* __restrict__ x, const int* __restrict__ batch,
        const float* __restrict__ pos,
        const float* __restrict__ msg_w1, const float* __restrict__ msg_b1,
        const float* __restrict__ gate_w, const float* __restrict__ gate_b) {
    __shared__ __align__(16) float sW1[64 * 32];
    __shared__ __align__(16) float sWg[32 * 32];
    int tid = threadIdx.x;
    for (int k = tid; k < 2048; k += 128) sW1[k] = msg_w1[k];
    for (int k = tid; k < 1024; k += 128) sWg[k] = gate_w[k];
    __syncthreads();

    int q = tid & 7;
    int c0 = q * 4;
    int n0 = blockIdx.x * 64 + (tid >> 3) * 4;
    if (n0 >= N_NODES) return;   // warp-uniform: 16 nodes/warp, 16 | 100000

    float xmA[4], xmB[4], xmC[4], xmD[4];
    {
        int bn = batch[n0];
        float4 sc = *(const float4*)&g_ss[bn * 64 + c0];
        float4 sh = *(const float4*)&g_ss[bn * 64 + 32 + c0];
        float4 xv = *(const float4*)&x[n0 * 32 + c0];
        xmA[0] = siluf(xv.x * (1.0f + sc.x) + sh.x);
        xmA[1] = siluf(xv.y * (1.0f + sc.y) + sh.y);
        xmA[2] = siluf(xv.z * (1.0f + sc.z) + sh.z);
        xmA[3] = siluf(xv.w * (1.0f + sc.w) + sh.w);
    }
    {
        int bn = batch[n0 + 1];
        float4 sc = *(const float4*)&g_ss[bn * 64 + c0];
        float4 sh = *(const float4*)&g_ss[bn * 64 + 32 + c0];
        float4 xv = *(const float4*)&x[(n0 + 1) * 32 + c0];
        xmB[0] = siluf(xv.x * (1.0f + sc.x) + sh.x);
        xmB[1] = siluf(xv.y * (1.0f + sc.y) + sh.y);
        xmB[2] = siluf(xv.z * (1.0f + sc.z) + sh.z);
        xmB[3] = siluf(xv.w * (1.0f + sc.w) + sh.w);
    }
    {
        int bn = batch[n0 + 2];
        float4 sc = *(const float4*)&g_ss[bn * 64 + c0];
        float4 sh = *(const float4*)&g_ss[bn * 64 + 32 + c0];
        float4 xv = *(const float4*)&x[(n0 + 2) * 32 + c0];
        xmC[0] = siluf(xv.x * (1.0f + sc.x) + sh.x);
        xmC[1] = siluf(xv.y * (1.0f + sc.y) + sh.y);
        xmC[2] = siluf(xv.z * (1.0f + sc.z) + sh.z);
        xmC[3] = siluf(xv.w * (1.0f + sc.w) + sh.w);
    }
    {
        int bn = batch[n0 + 3];
        float4 sc = *(const float4*)&g_ss[bn * 64 + c0];
        float4 sh = *(const float4*)&g_ss[bn * 64 + 32 + c0];
        float4 xv = *(const float4*)&x[(n0 + 3) * 32 + c0];
        xmD[0] = siluf(xv.x * (1.0f + sc.x) + sh.x);
        xmD[1] = siluf(xv.y * (1.0f + sc.y) + sh.y);
        xmD[2] = siluf(xv.z * (1.0f + sc.z) + sh.z);
        xmD[3] = siluf(xv.w * (1.0f + sc.w) + sh.w);
    }

    u64 aA[2], aB[2], aC[2], aD[2];
    u64 bA[2], bB[2], bC[2], bD[2];
    u64 gA[2], gB[2], gC[2], gD[2];
    {
        u64 m0 = pack2(msg_b1[c0], msg_b1[c0 + 1]);
        u64 m1 = pack2(msg_b1[c0 + 2], msg_b1[c0 + 3]);
        u64 g0 = pack2(gate_b[c0], gate_b[c0 + 1]);
        u64 g1 = pack2(gate_b[c0 + 2], gate_b[c0 + 3]);
        aA[0] = m0; aA[1] = m1; aB[0] = m0; aB[1] = m1;
        aC[0] = m0; aC[1] = m1; aD[0] = m0; aD[1] = m1;
        bA[0] = 0; bA[1] = 0; bB[0] = 0; bB[1] = 0;
        bC[0] = 0; bC[1] = 0; bD[0] = 0; bD[1] = 0;
        gA[0] = g0; gA[1] = g1; gB[0] = g0; gB[1] = g1;
        gC[0] = g0; gC[1] = g1; gD[0] = g0; gD[1] = g1;
    }
    #pragma unroll
    for (int kk = 0; kk < 32; kk++) {
        float vA = __shfl_sync(0xffffffffu, xmA[kk & 3], kk >> 2, 8);
        float vB = __shfl_sync(0xffffffffu, xmB[kk & 3], kk >> 2, 8);
        float vC = __shfl_sync(0xffffffffu, xmC[kk & 3], kk >> 2, 8);
        float vD = __shfl_sync(0xffffffffu, xmD[kk & 3], kk >> 2, 8);
        u64 vvA = pack2(vA, vA), vvB = pack2(vB, vB);
        u64 vvC = pack2(vC, vC), vvD = pack2(vD, vD);
        ulonglong2 wa = *(const ulonglong2*)&sW1[kk * 32 + c0];
        ulonglong2 wb = *(const ulonglong2*)&sW1[(32 + kk) * 32 + c0];
        ulonglong2 wg = *(const ulonglong2*)&sWg[kk * 32 + c0];
        ffma2(aA[0], wa.x, vvA); ffma2(aA[1], wa.y, vvA);
        ffma2(aB[0], wa.x, vvB); ffma2(aB[1], wa.y, vvB);
        ffma2(aC[0], wa.x, vvC); ffma2(aC[1], wa.y, vvC);
        ffma2(aD[0], wa.x, vvD); ffma2(aD[1], wa.y, vvD);
        ffma2(bA[0], wb.x, vvA); ffma2(bA[1], wb.y, vvA);
        ffma2(bB[0], wb.x, vvB); ffma2(bB[1], wb.y, vvB);
        ffma2(bC[0], wb.x, vvC); ffma2(bC[1], wb.y, vvC);
        ffma2(bD[0], wb.x, vvD); ffma2(bD[1], wb.y, vvD);
        ffma2(gA[0], wg.x, vvA); ffma2(gA[1], wg.y, vvA);
        ffma2(gB[0], wg.x, vvB); ffma2(gB[1], wg.y, vvB);
        ffma2(gC[0], wg.x, vvC); ffma2(gC[1], wg.y, vvC);
        ffma2(gD[0], wg.x, vvD); ffma2(gD[1], wg.y, vvD);
    }

    // stores per node
    float4 z = make_float4(0.f, 0.f, 0.f, 0.f);
    {
        *(float4*)&g_xm[n0 * 32 + c0] = make_float4(xmA[0], xmA[1], xmA[2], xmA[3]);
        *(ulonglong2*)&g_a[n0 * 32 + c0] = make_ulonglong2(aA[0], aA[1]);
        *(ulonglong2*)&g_b[n0 * 32 + c0] = make_ulonglong2(bA[0], bA[1]);
        float t0, t1, t2, t3;
        unpack2(gA[0], t0, t1); unpack2(gA[1], t2, t3);
        *(float4*)&g_gate[n0 * 32 + c0] =
            make_float4(sigmf(t0), sigmf(t1), sigmf(t2), sigmf(t3));
        *(float4*)&g_macc[n0 * 32 + c0] = z;
    }
    {
        int n = n0 + 1;
        *(float4*)&g_xm[n * 32 + c0] = make_float4(xmB[0], xmB[1], xmB[2], xmB[3]);
        *(ulonglong2*)&g_a[n * 32 + c0] = make_ulonglong2(aB[0], aB[1]);
        *(ulonglong2*)&g_b[n * 32 + c0] = make_ulonglong2(bB[0], bB[1]);
        float t0, t1, t2, t3;
        unpack2(gB[0], t0, t1); unpack2(gB[1], t2, t3);
        *(float4*)&g_gate[n * 32 + c0] =
            make_float4(sigmf(t0), sigmf(t1), sigmf(t2), sigmf(t3));
        *(float4*)&g_macc[n * 32 + c0] = z;
    }
    {
        int n = n0 + 2;
        *(float4*)&g_xm[n * 32 + c0] = make_float4(xmC[0], xmC[1], xmC[2], xmC[3]);
        *(ulonglong2*)&g_a[n * 32 + c0] = make_ulonglong2(aC[0], aC[1]);
        *(ulonglong2*)&g_b[n * 32 + c0] = make_ulonglong2(bC[0], bC[1]);
        float t0, t1, t2, t3;
        unpack2(gC[0], t0, t1); unpack2(gC[1], t2, t3);
        *(float4*)&g_gate[n * 32 + c0] =
            make_float4(sigmf(t0), sigmf(t1), sigmf(t2), sigmf(t3));
        *(float4*)&g_macc[n * 32 + c0] = z;
    }
    {
        int n = n0 + 3;
        *(float4*)&g_xm[n * 32 + c0] = make_float4(xmD[0], xmD[1], xmD[2], xmD[3]);
        *(ulonglong2*)&g_a[n * 32 + c0] = make_ulonglong2(aD[0], aD[1]);
        *(ulonglong2*)&g_b[n * 32 + c0] = make_ulonglong2(bD[0], bD[1]);
        float t0, t1, t2, t3;
        unpack2(gD[0], t0, t1); unpack2(gD[1], t2, t3);
        *(float4*)&g_gate[n * 32 + c0] =
            make_float4(sigmf(t0), sigmf(t1), sigmf(t2), sigmf(t3));
        *(float4*)&g_macc[n * 32 + c0] = z;
    }
    if (q < 4) {
        int n = n0 + q;
        *(float4*)&g_pacc[n * 4] = z;
        g_pos4[n] = make_float4(pos[n * 3], pos[n * 3 + 1], pos[n * 3 + 2], 0.0f);
    }
}

// ---------------- K3: edge kernel, 8 lanes/group x NE=4 edges ----------------
#define MV32X4(aA, aB, aC, aD, iA_, iB_, iC_, iD_, W, c0)                        \
    do {                                                                         \
        _Pragma("unroll")                                                        \
        for (int kk = 0; kk < 32; kk++) {                                        \
            float vA = __shfl_sync(0xffffffffu, iA_[kk & 3], kk >> 2, 8);        \
            float vB = __shfl_sync(0xffffffffu, iB_[kk & 3], kk >> 2, 8);        \
            float vC = __shfl_sync(0xffffffffu, iC_[kk & 3], kk >> 2, 8);        \
            float vD = __shfl_sync(0xffffffffu, iD_[kk & 3], kk >> 2, 8);        \
            u64 vvA = pack2(vA, vA), vvB = pack2(vB, vB);                        \
            u64 vvC = pack2(vC, vC), vvD = pack2(vD, vD);                        \
            ulonglong2 w = *(const ulonglong2*)&W[kk * 32 + c0];                 \
            ffma2(aA[0], w.x, vvA); ffma2(aA[1], w.y, vvA);                      \
            ffma2(aB[0], w.x, vvB); ffma2(aB[1], w.y, vvB);                      \
            ffma2(aC[0], w.x, vvC); ffma2(aC[1], w.y, vvC);                      \
            ffma2(aD[0], w.x, vvD); ffma2(aD[1], w.y, vvD);                      \
        }                                                                        \
    } while (0)

__global__ void __launch_bounds__(128) k_edge(
        const int* __restrict__ ei,
        const float* __restrict__ msg_w2, const float* __restrict__ msg_b2,
        const float* __restrict__ coord_w1, const float* __restrict__ coord_b1,
        const float* __restrict__ coord_w2, const float* __restrict__ coord_b2) {
    __shared__ __align__(16) float sW2[1024];
    __shared__ __align__(16) float sC1[1024];
    __shared__ float sC2[32], sB2[32], sCB1[32];
    __shared__ float sCB2;

    int tid = threadIdx.x;
    for (int k = tid; k < 1024; k += 128) {
        sW2[k] = msg_w2[k];
        sC1[k] = coord_w1[k];
    }
    if (tid < 32) {
        sC2[tid]  = coord_w2[tid];
        sB2[tid]  = msg_b2[tid];
        sCB1[tid] = coord_b1[tid];
    }
    if (tid == 0) sCB2 = coord_b2[0];
    __syncthreads();

    int q = tid & 7;
    int c0 = q * 4;
    int e0 = blockIdx.x * 64 + (tid >> 3) * 4;

    int4 iv = *(const int4*)&ei[e0];
    int4 jv = *(const int4*)&ei[E_EDGES + e0];

    int eq = q & 3;
    int i_own = (eq & 2) ? ((eq & 1) ? iv.w : iv.z) : ((eq & 1) ? iv.y : iv.x);
    int j_own = (eq & 2) ? ((eq & 1) ? jv.w : jv.z) : ((eq & 1) ? jv.y : jv.x);
    float4 pi = g_pos4[i_own], pj = g_pos4[j_own];
    float dx = pi.x - pj.x, dy = pi.y - pj.y, dz = pi.z - pj.z;
    float dist = sqrtf(dx * dx + dy * dy + dz * dz);
    float u = fminf(dist, D_CUT) * ((float)(TAB - 1) / D_CUT);
    int i0_own = min((int)(u + 0.5f), TAB - 1);

    int i0A = __shfl_sync(0xffffffffu, i0_own, 0, 8);
    int i0B = __shfl_sync(0xffffffffu, i0_own, 1, 8);
    int i0C = __shfl_sync(0xffffffffu, i0_own, 2, 8);
    int i0D = __shfl_sync(0xffffffffu, i0_own, 3, 8);

    float hA[4], egA[4], hB[4], egB[4], hC[4], egC[4], hD[4], egD[4];
    {
        float4 a = *(const float4*)&g_a[iv.x * 32 + c0];
        float4 b = *(const float4*)&g_b[jv.x * 32 + c0];
        float4 t = *(const float4*)&g_tab[i0A * 32 + c0];
        float4 g = *(const float4*)&g_gate[jv.x * 32 + c0];
        hA[0] = siluf(a.x + b.x); hA[1] = siluf(a.y + b.y);
        hA[2] = siluf(a.z + b.z); hA[3] = siluf(a.w + b.w);
        egA[0] = t.x * g.x; egA[1] = t.y * g.y; egA[2] = t.z * g.z; egA[3] = t.w * g.w;
    }
    {
        float4 a = *(const float4*)&g_a[iv.y * 32 + c0];
        float4 b = *(const float4*)&g_b[jv.y * 32 + c0];
        float4 t = *(const float4*)&g_tab[i0B * 32 + c0];
        float4 g = *(const float4*)&g_gate[jv.y * 32 + c0];
        hB[0] = siluf(a.x + b.x); hB[1] = siluf(a.y + b.y);
        hB[2] = siluf(a.z + b.z); hB[3] = siluf(a.w + b.w);
        egB[0] = t.x * g.x; egB[1] = t.y * g.y; egB[2] = t.z * g.z; egB[3] = t.w * g.w;
    }
    {
        float4 a = *(const float4*)&g_a[iv.z * 32 + c0];
        float4 b = *(const float4*)&g_b[jv.z * 32 + c0];
        float4 t = *(const float4*)&g_tab[i0C * 32 + c0];
        float4 g = *(const float4*)&g_gate[jv.z * 32 + c0];
        hC[0] = siluf(a.x + b.x); hC[1] = siluf(a.y + b.y);
        hC[2] = siluf(a.z + b.z); hC[3] = siluf(a.w + b.w);
        egC[0] = t.x * g.x; egC[1] = t.y * g.y; egC[2] = t.z * g.z; egC[3] = t.w * g.w;
    }
    {
        float4 a = *(const float4*)&g_a[iv.w * 32 + c0];
        float4 b = *(const float4*)&g_b[jv.w * 32 + c0];
        float4 t = *(const float4*)&g_tab[i0D * 32 + c0];
        float4 g = *(const float4*)&g_gate[jv.w * 32 + c0];
        hD[0] = siluf(a.x + b.x); hD[1] = siluf(a.y + b.y);
        hD[2] = siluf(a.z + b.z); hD[3] = siluf(a.w + b.w);
        egD[0] = t.x * g.x; egD[1] = t.y * g.y; egD[2] = t.z * g.z; egD[3] = t.w * g.w;
    }

    u64 mmA[2], mmB[2], mmC[2], mmD[2];
    {
        u64 b0 = pack2(sB2[c0], sB2[c0 + 1]);
        u64 b1 = pack2(sB2[c0 + 2], sB2[c0 + 3]);
        mmA[0] = b0; mmA[1] = b1; mmB[0] = b0; mmB[1] = b1;
        mmC[0] = b0; mmC[1] = b1; mmD[0] = b0; mmD[1] = b1;
    }
    MV32X4(mmA, mmB, mmC, mmD, hA, hB, hC, hD, sW2, c0);

    float mA[4], mB[4], mC[4], mD[4];
    {
        float t0, t1;
        unpack2(mmA[0], t0, t1); mA[0] = siluf(t0) * egA[0]; mA[1] = siluf(t1) * egA[1];
        unpack2(mmA[1], t0, t1); mA[2] = siluf(t0) * egA[2]; mA[3] = siluf(t1) * egA[3];
        unpack2(mmB[0], t0, t1); mB[0] = siluf(t0) * egB[0]; mB[1] = siluf(t1) * egB[1];
        unpack2(mmB[1], t0, t1); mB[2] = siluf(t0) * egB[2]; mB[3] = siluf(t1) * egB[3];
        unpack2(mmC[0], t0, t1); mC[0] = siluf(t0) * egC[0]; mC[1] = siluf(t1) * egC[1];
        unpack2(mmC[1], t0, t1); mC[2] = siluf(t0) * egC[2]; mC[3] = siluf(t1) * egC[3];
        unpack2(mmD[0], t0, t1); mD[0] = siluf(t0) * egD[0]; mD[1] = siluf(t1) * egD[1];
        unpack2(mmD[1], t0, t1); mD[2] = siluf(t0) * egD[2]; mD[3] = siluf(t1) * egD[3];
    }

    red_v4(&g_macc[jv.x * 32 + c0], mA[0], mA[1], mA[2], mA[3]);
    red_v4(&g_macc[jv.y * 32 + c0], mB[0], mB[1], mB[2], mB[3]);
    red_v4(&g_macc[jv.z * 32 + c0], mC[0], mC[1], mC[2], mC[3]);
    red_v4(&g_macc[jv.w * 32 + c0], mD[0], mD[1], mD[2], mD[3]);

    u64 stA[2], stB[2], stC[2], stD[2];
    {
        u64 b0 = pack2(sCB1[c0], sCB1[c0 + 1]);
        u64 b1 = pack2(sCB1[c0 + 2], sCB1[c0 + 3]);
        stA[0] = b0; stA[1] = b1; stB[0] = b0; stB[1] = b1;
        stC[0] = b0; stC[1] = b1; stD[0] = b0; stD[1] = b1;
    }
    MV32X4(stA, stB, stC, stD, mA, mB, mC, mD, sC1, c0);

    float w0 = sC2[c0], w1 = sC2[c0 + 1], w2 = sC2[c0 + 2], w3 = sC2[c0 + 3];
    float spA, spB, spC, spD;
    {
        float t0, t1, t2, t3;
        unpack2(stA[0], t0, t1); unpack2(stA[1], t2, t3);
        spA = siluf(t0) * w0 + siluf(t1) * w1 + siluf(t2) * w2 + siluf(t3) * w3;
        unpack2(stB[0], t0, t1); unpack2(stB[1], t2, t3);
        spB = siluf(t0) * w0 + siluf(t1) * w1 + siluf(t2) * w2 + siluf(t3) * w3;
        unpack2(stC[0], t0, t1); unpack2(stC[1], t2, t3);
        spC = siluf(t0) * w0 + siluf(t1) * w1 + siluf(t2) * w2 + siluf(t3) * w3;
        unpack2(stD[0], t0, t1); unpack2(stD[1], t2, t3);
        spD = siluf(t0) * w0 + siluf(t1) * w1 + siluf(t2) * w2 + siluf(t3) * w3;
    }
    spA += __shfl_xor_sync(0xffffffffu, spA, 1);
    spA += __shfl_xor_sync(0xffffffffu, spA, 2);
    spA += __shfl_xor_sync(0xffffffffu, spA, 4);
    spB += __shfl_xor_sync(0xffffffffu, spB, 1);
    spB += __shfl_xor_sync(0xffffffffu, spB, 2);
    spB += __shfl_xor_sync(0xffffffffu, spB, 4);
    spC += __shfl_xor_sync(0xffffffffu, spC, 1);
    spC += __shfl_xor_sync(0xffffffffu, spC, 2);
    spC += __shfl_xor_sync(0xffffffffu, spC, 4);
    spD += __shfl_xor_sync(0xffffffffu, spD, 1);
    spD += __shfl_xor_sync(0xffffffffu, spD, 2);
    spD += __shfl_xor_sync(0xffffffffu, spD, 4);

    if (q < 4) {
        float s_own = (q & 2) ? ((q & 1) ? spD : spC) : ((q & 1) ? spB : spA);
        s_own += sCB2;
        red_v4(&g_pacc[j_own * 4], dx * s_own, dy * s_own, dz * s_own, 1.0f);
    }
}

// ---------------- K4: combine + outputs, 8 lanes x NE=4 nodes ---------------
// MV1 (K=64): lane owns input slice [q*8, q*8+8) of concat(xm, macc).
__global__ void __launch_bounds__(128) k_final(
        const float* __restrict__ pos,
        const float* __restrict__ comb_w1, const float* __restrict__ cb1,
        const float* __restrict__ comb_w2, const float* __restrict__ cb2,
        float* __restrict__ outx, float* __restrict__ outp) {
    __shared__ __align__(16) float sW1[64 * 32];
    __shared__ __align__(16) float sW2[32 * 32];
    int tid = threadIdx.x;
    for (int k = tid; k < 2048; k += 128) sW1[k] = comb_w1[k];
    for (int k = tid; k < 1024; k += 128) sW2[k] = comb_w2[k];
    __syncthreads();

    int q = tid & 7;
    int c0 = q * 4;
    int n0 = blockIdx.x * 64 + (tid >> 3) * 4;
    if (n0 >= N_NODES) return;   // warp-uniform
    // input slice for K=64 broadcast: lane q owns concat[q*8 .. q*8+8)
    int half = (q & 3) * 8;   // offset within the 32-float source array

    float inA[8], inB[8], inC[8], inD[8];
    {
        const float* src = (q < 4) ? &g_xm[n0 * 32] : &g_macc[n0 * 32];
        float4 v0 = *(const float4*)&src[half];
        float4 v1 = *(const float4*)&src[half + 4];
        inA[0] = v0.x; inA[1] = v0.y; inA[2] = v0.z; inA[3] = v0.w;
        inA[4] = v1.x; inA[5] = v1.y; inA[6] = v1.z; inA[7] = v1.w;
    }
    {
        const float* src = (q < 4) ? &g_xm[(n0 + 1) * 32] : &g_macc[(n0 + 1) * 32];
        float4 v0 = *(const float4*)&src[half];
        float4 v1 = *(const float4*)&src[half + 4];
        inB[0] = v0.x; inB[1] = v0.y; inB[2] = v0.z; inB[3] = v0.w;
        inB[4] = v1.x; inB[5] = v1.y; inB[6] = v1.z; inB[7] = v1.w;
    }
    {
        const float* src = (q < 4) ? &g_xm[(n0 + 2) * 32] : &g_macc[(n0 + 2) * 32];
        float4 v0 = *(const float4*)&src[half];
        float4 v1 = *(const float4*)&src[half + 4];
        inC[0] = v0.x; inC[1] = v0.y; inC[2] = v0.z; inC[3] = v0.w;
        inC[4] = v1.x; inC[5] = v1.y; inC[6] = v1.z; inC[7] = v1.w;
    }
    {
        const float* src = (q < 4) ? &g_xm[(n0 + 3) * 32] : &g_macc[(n0 + 3) * 32];
        float4 v0 = *(const float4*)&src[half];
        float4 v1 = *(const float4*)&src[half + 4];
        inD[0] = v0.x; inD[1] = v0.y; inD[2] = v0.z; inD[3] = v0.w;
        inD[4] = v1.x; inD[5] = v1.y; inD[6] = v1.z; inD[7] = v1.w;
    }

    u64 accA[2], accB[2], accC[2], accD[2];
    {
        u64 b0 = pack2(cb1[c0], cb1[c0 + 1]);
        u64 b1 = pack2(cb1[c0 + 2], cb1[c0 + 3]);
        accA[0] = b0; accA[1] = b1; accB[0] = b0; accB[1] = b1;
        accC[0] = b0; accC[1] = b1; accD[0] = b0; accD[1] = b1;
    }
    #pragma unroll
    for (int kk = 0; kk < 64; kk++) {
        float vA = __shfl_sync(0xffffffffu, inA[kk & 7], kk >> 3, 8);
        float vB = __shfl_sync(0xffffffffu, inB[kk & 7], kk >> 3, 8);
        float vC = __shfl_sync(0xffffffffu, inC[kk & 7], kk >> 3, 8);
        float vD = __shfl_sync(0xffffffffu, inD[kk & 7], kk >> 3, 8);
        u64 vvA = pack2(vA, vA), vvB = pack2(vB, vB);
        u64 vvC = pack2(vC, vC), vvD = pack2(vD, vD);
        ulonglong2 w = *(const ulonglong2*)&sW1[kk * 32 + c0];
        ffma2(accA[0], w.x, vvA); ffma2(accA[1], w.y, vvA);
        ffma2(accB[0], w.x, vvB); ffma2(accB[1], w.y, vvB);
        ffma2(accC[0], w.x, vvC); ffma2(accC[1], w.y, vvC);
        ffma2(accD[0], w.x, vvD); ffma2(accD[1], w.y, vvD);
    }
    float hhA[4], hhB[4], hhC[4], hhD[4];
    {
        float t0, t1;
        unpack2(accA[0], t0, t1); hhA[0] = siluf(t0); hhA[1] = siluf(t1);
        unpack2(accA[1], t0, t1); hhA[2] = siluf(t0); hhA[3] = siluf(t1);
        unpack2(accB[0], t0, t1); hhB[0] = siluf(t0); hhB[1] = siluf(t1);
        unpack2(accB[1], t0, t1); hhB[2] = siluf(t0); hhB[3] = siluf(t1);
        unpack2(accC[0], t0, t1); hhC[0] = siluf(t0); hhC[1] = siluf(t1);
        unpack2(accC[1], t0, t1); hhC[2] = siluf(t0); hhC[3] = siluf(t1);
        unpack2(accD[0], t0, t1); hhD[0] = siluf(t0); hhD[1] = siluf(t1);
        unpack2(accD[1], t0, t1); hhD[2] = siluf(t0); hhD[3] = siluf(t1);
    }

    u64 a2A[2], a2B[2], a2C[2], a2D[2];
    {
        u64 b0 = pack2(cb2[c0], cb2[c0 + 1]);
        u64 b1 = pack2(cb2[c0 + 2], cb2[c0 + 3]);
        a2A[0] = b0; a2A[1] = b1; a2B[0] = b0; a2B[1] = b1;
        a2C[0] = b0; a2C[1] = b1; a2D[0] = b0; a2D[1] = b1;
    }
    MV32X4(a2A, a2B, a2C, a2D, hhA, hhB, hhC, hhD, sW2, c0);

    {
        float t0, t1, t2, t3;
        unpack2(a2A[0], t0, t1); unpack2(a2A[1], t2, t3);
        float4 xm = *(const float4*)&g_xm[n0 * 32 + c0];
        *(float4*)&outx[n0 * 32 + c0] = make_float4(
            siluf(xm.x + t0), siluf(xm.y + t1), siluf(xm.z + t2), siluf(xm.w + t3));
    }
    {
        int n = n0 + 1;
        float t0, t1, t2, t3;
        unpack2(a2B[0], t0, t1); unpack2(a2B[1], t2, t3);
        float4 xm = *(const float4*)&g_xm[n * 32 + c0];
        *(float4*)&outx[n * 32 + c0] = make_float4(
            siluf(xm.x + t0), siluf(xm.y + t1), siluf(xm.z + t2), siluf(xm.w + t3));
    }
    {
        int n = n0 + 2;
        float t0, t1, t2, t3;
        unpack2(a2C[0], t0, t1); unpack2(a2C[1], t2, t3);
        float4 xm = *(const float4*)&g_xm[n * 32 + c0];
        *(float4*)&outx[n * 32 + c0] = make_float4(
            siluf(xm.x + t0), siluf(xm.y + t1), siluf(xm.z + t2), siluf(xm.w + t3));
    }
    {
        int n = n0 + 3;
        float t0, t1, t2, t3;
        unpack2(a2D[0], t0, t1); unpack2(a2D[1], t2, t3);
        float4 xm = *(const float4*)&g_xm[n * 32 + c0];
        *(float4*)&outx[n * 32 + c0] = make_float4(
            siluf(xm.x + t0), siluf(xm.y + t1), siluf(xm.z + t2), siluf(xm.w + t3));
    }

    if (q < 4) {
        int n = n0 + q;
        float4 pa = *(const float4*)&g_pacc[n * 4];
        float ic = 1.0f / fmaxf(pa.w, 1.0f);
        outp[n * 3 + 0] = pos[n * 3 + 0] + pa.x * ic;
        outp[n * 3 + 1] = pos[n * 3 + 1] + pa.y * ic;
        outp[n * 3 + 2] = pos[n * 3 + 2] + pa.z * ic;
    }
}

// ---------------- launch ----------------
extern "C" void kernel_launch(void* const* d_in, const int* in_sizes, int n_in,
                              void* d_out, int out_size) {
    const float* x        = (const float*)d_in[0];
    const int*   ei       = (const int*)d_in[1];
    const float* pos      = (const float*)d_in[2];
    const float* time     = (const float*)d_in[3];
    const int*   batch    = (const int*)d_in[4];
    const float* means    = (const float*)d_in[5];
    const float* betas    = (const float*)d_in[6];
    const float* w_dist   = (const float*)d_in[7];
    const float* msg_w1   = (const float*)d_in[8];
    const float* msg_b1   = (const float*)d_in[9];
    const float* msg_w2   = (const float*)d_in[10];
    const float* msg_b2   = (const float*)d_in[11];
    const float* gate_w   = (const float*)d_in[12];
    const float* gate_b   = (const float*)d_in[13];
    const float* time_w1  = (const float*)d_in[14];
    const float* time_b1  = (const float*)d_in[15];
    const float* time_w2  = (const float*)d_in[16];
    const float* time_b2  = (const float*)d_in[17];
    const float* comb_w1  = (const float*)d_in[18];
    const float* comb_b1  = (const float*)d_in[19];
    const float* comb_w2  = (const float*)d_in[20];
    const float* comb_b2  = (const float*)d_in[21];
    const float* coord_w1 = (const float*)d_in[22];
    const float* coord_b1 = (const float*)d_in[23];
    const float* coord_w2 = (const float*)d_in[24];
    const float* coord_b2 = (const float*)d_in[25];

    float* outx = (float*)d_out;
    float* outp = (float*)d_out + N_NODES * 32;

    k_time<<<G_GRAPHS / 4 + TAB / 8, 256>>>(time, time_w1, time_b1, time_w2, time_b2,
                                            means, betas, w_dist);
    k_node<<<NODE_BLOCKS, 128>>>(x, batch, pos, msg_w1, msg_b1, gate_w, gate_b);
    k_edge<<<E_EDGES / 64, 128>>>(ei, msg_w2, msg_b2,
                                  coord_w1, coord_b1, coord_w2, coord_b2);
    k_final<<<NODE_BLOCKS, 128>>>(pos, comb_w1, comb_b1, comb_w2, comb_b2,
                                  outx, outp);
}

// round 13
// speedup vs baseline: 1.4189x; 1.0727x over previous
#include <cuda_runtime.h>
#include <math.h>

#define N_NODES 100000
#define E_EDGES 800000
#define G_GRAPHS 512
#define HID 32
#define D_CUT 5.0f
#define TAB 8192
#define NODE_TILES 1563   // ceil(100000/64)
#define EDGE_TILES 12500  // 800000/64

typedef unsigned long long u64;

// ---------------- scratch (static, no allocation) ----------------
__device__ __align__(16) float g_ss[G_GRAPHS * 64];
__device__ __align__(16) float g_xm[N_NODES * 32];
__device__ __align__(16) float g_a[N_NODES * 32];
__device__ __align__(16) float g_b[N_NODES * 32];
__device__ __align__(16) float g_gate[N_NODES * 32];
__device__ __align__(16) float g_macc[N_NODES * 32];
__device__ __align__(16) float g_pacc[N_NODES * 4];
__device__ __align__(16) float4 g_pos4[N_NODES];
__device__ __align__(16) float g_tab[TAB * 32];

__device__ __forceinline__ float siluf(float v) { return v / (1.0f + __expf(-v)); }
__device__ __forceinline__ float sigmf(float v) { return 1.0f / (1.0f + __expf(-v)); }

__device__ __forceinline__ void red_v4(float* p, float a, float b, float c, float d) {
    asm volatile("red.global.add.v4.f32 [%0], {%1,%2,%3,%4};"
                 :: "l"(p), "f"(a), "f"(b), "f"(c), "f"(d) : "memory");
}

__device__ __forceinline__ u64 pack2(float lo, float hi) {
    u64 r; asm("mov.b64 %0, {%1, %2};" : "=l"(r) : "f"(lo), "f"(hi)); return r;
}
__device__ __forceinline__ void unpack2(u64 v, float& lo, float& hi) {
    asm("mov.b64 {%0, %1}, %2;" : "=f"(lo), "=f"(hi) : "l"(v));
}
__device__ __forceinline__ void ffma2(u64& d, u64 a, u64 b) {
    asm("fma.rn.f32x2 %0, %1, %2, %0;" : "+l"(d) : "l"(a), "l"(b));
}

// ---------------- K1: time MLP + dist_emb table (fused) ----------------
__global__ void __launch_bounds__(256) k_time(
        const float* __restrict__ time,
        const float* __restrict__ w1, const float* __restrict__ b1,
        const float* __restrict__ w2, const float* __restrict__ b2,
        const float* __restrict__ means, const float* __restrict__ betas,
        const float* __restrict__ w_dist) {
    int tid = threadIdx.x;
    if (blockIdx.x >= G_GRAPHS / 4) {
        __shared__ float sW[1024];
        __shared__ float sMu[32], sBeta[32];
        for (int k = tid; k < 1024; k += 256) sW[k] = w_dist[k];
        if (tid < 32) { sMu[tid] = means[tid]; sBeta[tid] = betas[tid]; }
        __syncthreads();
        int r = (blockIdx.x - G_GRAPHS / 4) * 8 + (tid >> 5);
        int c = tid & 31;
        float d = (float)r * (D_CUT / (float)(TAB - 1));
        float cutoff = 0.5f * (__cosf(d * (3.14159265358979f / D_CUT)) + 1.0f);
        float ed = __expf(-d);
        float acc = 0.0f;
        #pragma unroll 8
        for (int k = 0; k < 32; k++) {
            float t = ed - sMu[k];
            acc += __expf(-sBeta[k] * t * t) * sW[k * 32 + c];
        }
        g_tab[r * 32 + c] = cutoff * acc;
        return;
    }
    __shared__ float trow[4][128];
    __shared__ float hid[4][64];
    int gsub = tid >> 6;
    int t = tid & 63;
    int g = blockIdx.x * 4 + gsub;
    trow[gsub][t]      = time[g * 128 + t];
    trow[gsub][t + 64] = time[g * 128 + 64 + t];
    __syncthreads();
    float acc = b1[t];
    #pragma unroll 8
    for (int k = 0; k < 128; k++) acc += trow[gsub][k] * w1[k * 64 + t];
    hid[gsub][t] = siluf(acc);
    __syncthreads();
    float acc2 = b2[t];
    #pragma unroll 8
    for (int k = 0; k < 64; k++) acc2 += hid[gsub][k] * w2[k * 64 + t];
    g_ss[g * 64 + t] = acc2;
}

// ---------------- K2: per-node precompute, persistent, 8 lanes x NE=4 -------
__global__ void __launch_bounds__(128) k_node(
        const float* __restrict__ x, const int* __restrict__ batch,
        const float* __restrict__ pos,
        const float* __restrict__ msg_w1, const float* __restrict__ msg_b1,
        const float* __restrict__ gate_w, const float* __restrict__ gate_b) {
    __shared__ __align__(16) float sW1[64 * 32];
    __shared__ __align__(16) float sWg[32 * 32];
    int tid = threadIdx.x;
    for (int k = tid; k < 2048; k += 128) sW1[k] = msg_w1[k];
    for (int k = tid; k < 1024; k += 128) sWg[k] = gate_w[k];
    __syncthreads();

    int q = tid & 7;
    int c0 = q * 4;

    u64 mbias0 = pack2(msg_b1[c0], msg_b1[c0 + 1]);
    u64 mbias1 = pack2(msg_b1[c0 + 2], msg_b1[c0 + 3]);
    u64 gbias0 = pack2(gate_b[c0], gate_b[c0 + 1]);
    u64 gbias1 = pack2(gate_b[c0 + 2], gate_b[c0 + 3]);

    for (int tile = blockIdx.x; tile < NODE_TILES; tile += gridDim.x) {
        int n0 = tile * 64 + (tid >> 3) * 4;
        if (n0 >= N_NODES) continue;   // warp-uniform

        float xmA[4], xmB[4], xmC[4], xmD[4];
        {
            int bn = batch[n0];
            float4 sc = *(const float4*)&g_ss[bn * 64 + c0];
            float4 sh = *(const float4*)&g_ss[bn * 64 + 32 + c0];
            float4 xv = *(const float4*)&x[n0 * 32 + c0];
            xmA[0] = siluf(xv.x * (1.0f + sc.x) + sh.x);
            xmA[1] = siluf(xv.y * (1.0f + sc.y) + sh.y);
            xmA[2] = siluf(xv.z * (1.0f + sc.z) + sh.z);
            xmA[3] = siluf(xv.w * (1.0f + sc.w) + sh.w);
        }
        {
            int bn = batch[n0 + 1];
            float4 sc = *(const float4*)&g_ss[bn * 64 + c0];
            float4 sh = *(const float4*)&g_ss[bn * 64 + 32 + c0];
            float4 xv = *(const float4*)&x[(n0 + 1) * 32 + c0];
            xmB[0] = siluf(xv.x * (1.0f + sc.x) + sh.x);
            xmB[1] = siluf(xv.y * (1.0f + sc.y) + sh.y);
            xmB[2] = siluf(xv.z * (1.0f + sc.z) + sh.z);
            xmB[3] = siluf(xv.w * (1.0f + sc.w) + sh.w);
        }
        {
            int bn = batch[n0 + 2];
            float4 sc = *(const float4*)&g_ss[bn * 64 + c0];
            float4 sh = *(const float4*)&g_ss[bn * 64 + 32 + c0];
            float4 xv = *(const float4*)&x[(n0 + 2) * 32 + c0];
            xmC[0] = siluf(xv.x * (1.0f + sc.x) + sh.x);
            xmC[1] = siluf(xv.y * (1.0f + sc.y) + sh.y);
            xmC[2] = siluf(xv.z * (1.0f + sc.z) + sh.z);
            xmC[3] = siluf(xv.w * (1.0f + sc.w) + sh.w);
        }
        {
            int bn = batch[n0 + 3];
            float4 sc = *(const float4*)&g_ss[bn * 64 + c0];
            float4 sh = *(const float4*)&g_ss[bn * 64 + 32 + c0];
            float4 xv = *(const float4*)&x[(n0 + 3) * 32 + c0];
            xmD[0] = siluf(xv.x * (1.0f + sc.x) + sh.x);
            xmD[1] = siluf(xv.y * (1.0f + sc.y) + sh.y);
            xmD[2] = siluf(xv.z * (1.0f + sc.z) + sh.z);
            xmD[3] = siluf(xv.w * (1.0f + sc.w) + sh.w);
        }

        u64 aA[2], aB[2], aC[2], aD[2];
        u64 bA[2], bB[2], bC[2], bD[2];
        u64 gA[2], gB[2], gC[2], gD[2];
        aA[0] = mbias0; aA[1] = mbias1; aB[0] = mbias0; aB[1] = mbias1;
        aC[0] = mbias0; aC[1] = mbias1; aD[0] = mbias0; aD[1] = mbias1;
        bA[0] = 0; bA[1] = 0; bB[0] = 0; bB[1] = 0;
        bC[0] = 0; bC[1] = 0; bD[0] = 0; bD[1] = 0;
        gA[0] = gbias0; gA[1] = gbias1; gB[0] = gbias0; gB[1] = gbias1;
        gC[0] = gbias0; gC[1] = gbias1; gD[0] = gbias0; gD[1] = gbias1;

        #pragma unroll
        for (int kk = 0; kk < 32; kk++) {
            float vA = __shfl_sync(0xffffffffu, xmA[kk & 3], kk >> 2, 8);
            float vB = __shfl_sync(0xffffffffu, xmB[kk & 3], kk >> 2, 8);
            float vC = __shfl_sync(0xffffffffu, xmC[kk & 3], kk >> 2, 8);
            float vD = __shfl_sync(0xffffffffu, xmD[kk & 3], kk >> 2, 8);
            u64 vvA = pack2(vA, vA), vvB = pack2(vB, vB);
            u64 vvC = pack2(vC, vC), vvD = pack2(vD, vD);
            ulonglong2 wa = *(const ulonglong2*)&sW1[kk * 32 + c0];
            ulonglong2 wb = *(const ulonglong2*)&sW1[(32 + kk) * 32 + c0];
            ulonglong2 wg = *(const ulonglong2*)&sWg[kk * 32 + c0];
            ffma2(aA[0], wa.x, vvA); ffma2(aA[1], wa.y, vvA);
            ffma2(aB[0], wa.x, vvB); ffma2(aB[1], wa.y, vvB);
            ffma2(aC[0], wa.x, vvC); ffma2(aC[1], wa.y, vvC);
            ffma2(aD[0], wa.x, vvD); ffma2(aD[1], wa.y, vvD);
            ffma2(bA[0], wb.x, vvA); ffma2(bA[1], wb.y, vvA);
            ffma2(bB[0], wb.x, vvB); ffma2(bB[1], wb.y, vvB);
            ffma2(bC[0], wb.x, vvC); ffma2(bC[1], wb.y, vvC);
            ffma2(bD[0], wb.x, vvD); ffma2(bD[1], wb.y, vvD);
            ffma2(gA[0], wg.x, vvA); ffma2(gA[1], wg.y, vvA);
            ffma2(gB[0], wg.x, vvB); ffma2(gB[1], wg.y, vvB);
            ffma2(gC[0], wg.x, vvC); ffma2(gC[1], wg.y, vvC);
            ffma2(gD[0], wg.x, vvD); ffma2(gD[1], wg.y, vvD);
        }

        float4 z = make_float4(0.f, 0.f, 0.f, 0.f);
        {
            *(float4*)&g_xm[n0 * 32 + c0] = make_float4(xmA[0], xmA[1], xmA[2], xmA[3]);
            *(ulonglong2*)&g_a[n0 * 32 + c0] = make_ulonglong2(aA[0], aA[1]);
            *(ulonglong2*)&g_b[n0 * 32 + c0] = make_ulonglong2(bA[0], bA[1]);
            float t0, t1, t2, t3;
            unpack2(gA[0], t0, t1); unpack2(gA[1], t2, t3);
            *(float4*)&g_gate[n0 * 32 + c0] =
                make_float4(sigmf(t0), sigmf(t1), sigmf(t2), sigmf(t3));
            *(float4*)&g_macc[n0 * 32 + c0] = z;
        }
        {
            int n = n0 + 1;
            *(float4*)&g_xm[n * 32 + c0] = make_float4(xmB[0], xmB[1], xmB[2], xmB[3]);
            *(ulonglong2*)&g_a[n * 32 + c0] = make_ulonglong2(aB[0], aB[1]);
            *(ulonglong2*)&g_b[n * 32 + c0] = make_ulonglong2(bB[0], bB[1]);
            float t0, t1, t2, t3;
            unpack2(gB[0], t0, t1); unpack2(gB[1], t2, t3);
            *(float4*)&g_gate[n * 32 + c0] =
                make_float4(sigmf(t0), sigmf(t1), sigmf(t2), sigmf(t3));
            *(float4*)&g_macc[n * 32 + c0] = z;
        }
        {
            int n = n0 + 2;
            *(float4*)&g_xm[n * 32 + c0] = make_float4(xmC[0], xmC[1], xmC[2], xmC[3]);
            *(ulonglong2*)&g_a[n * 32 + c0] = make_ulonglong2(aC[0], aC[1]);
            *(ulonglong2*)&g_b[n * 32 + c0] = make_ulonglong2(bC[0], bC[1]);
            float t0, t1, t2, t3;
            unpack2(gC[0], t0, t1); unpack2(gC[1], t2, t3);
            *(float4*)&g_gate[n * 32 + c0] =
                make_float4(sigmf(t0), sigmf(t1), sigmf(t2), sigmf(t3));
            *(float4*)&g_macc[n * 32 + c0] = z;
        }
        {
            int n = n0 + 3;
            *(float4*)&g_xm[n * 32 + c0] = make_float4(xmD[0], xmD[1], xmD[2], xmD[3]);
            *(ulonglong2*)&g_a[n * 32 + c0] = make_ulonglong2(aD[0], aD[1]);
            *(ulonglong2*)&g_b[n * 32 + c0] = make_ulonglong2(bD[0], bD[1]);
            float t0, t1, t2, t3;
            unpack2(gD[0], t0, t1); unpack2(gD[1], t2, t3);
            *(float4*)&g_gate[n * 32 + c0] =
                make_float4(sigmf(t0), sigmf(t1), sigmf(t2), sigmf(t3));
            *(float4*)&g_macc[n * 32 + c0] = z;
        }
        if (q < 4) {
            int n = n0 + q;
            *(float4*)&g_pacc[n * 4] = z;
            g_pos4[n] = make_float4(pos[n * 3], pos[n * 3 + 1], pos[n * 3 + 2], 0.0f);
        }
    }
}

// ---------------- K3: edge kernel, persistent, 8 lanes/group x NE=4 ---------
#define MV32X4(aA, aB, aC, aD, iA_, iB_, iC_, iD_, W, c0)                        \
    do {                                                                         \
        _Pragma("unroll")                                                        \
        for (int kk = 0; kk < 32; kk++) {                                        \
            float vA = __shfl_sync(0xffffffffu, iA_[kk & 3], kk >> 2, 8);        \
            float vB = __shfl_sync(0xffffffffu, iB_[kk & 3], kk >> 2, 8);        \
            float vC = __shfl_sync(0xffffffffu, iC_[kk & 3], kk >> 2, 8);        \
            float vD = __shfl_sync(0xffffffffu, iD_[kk & 3], kk >> 2, 8);        \
            u64 vvA = pack2(vA, vA), vvB = pack2(vB, vB);                        \
            u64 vvC = pack2(vC, vC), vvD = pack2(vD, vD);                        \
            ulonglong2 w = *(const ulonglong2*)&W[kk * 32 + c0];                 \
            ffma2(aA[0], w.x, vvA); ffma2(aA[1], w.y, vvA);                      \
            ffma2(aB[0], w.x, vvB); ffma2(aB[1], w.y, vvB);                      \
            ffma2(aC[0], w.x, vvC); ffma2(aC[1], w.y, vvC);                      \
            ffma2(aD[0], w.x, vvD); ffma2(aD[1], w.y, vvD);                      \
        }                                                                        \
    } while (0)

__global__ void __launch_bounds__(128) k_edge(
        const int* __restrict__ ei,
        const float* __restrict__ msg_w2, const float* __restrict__ msg_b2,
        const float* __restrict__ coord_w1, const float* __restrict__ coord_b1,
        const float* __restrict__ coord_w2, const float* __restrict__ coord_b2) {
    __shared__ __align__(16) float sW2[1024];
    __shared__ __align__(16) float sC1[1024];
    __shared__ float sC2[32], sB2[32], sCB1[32];
    __shared__ float sCB2;

    int tid = threadIdx.x;
    for (int k = tid; k < 1024; k += 128) {
        sW2[k] = msg_w2[k];
        sC1[k] = coord_w1[k];
    }
    if (tid < 32) {
        sC2[tid]  = coord_w2[tid];
        sB2[tid]  = msg_b2[tid];
        sCB1[tid] = coord_b1[tid];
    }
    if (tid == 0) sCB2 = coord_b2[0];
    __syncthreads();

    int q = tid & 7;
    int c0 = q * 4;

    u64 mb0 = pack2(sB2[c0], sB2[c0 + 1]);
    u64 mb1 = pack2(sB2[c0 + 2], sB2[c0 + 3]);
    u64 cb0 = pack2(sCB1[c0], sCB1[c0 + 1]);
    u64 cb1v = pack2(sCB1[c0 + 2], sCB1[c0 + 3]);
    float w0 = sC2[c0], w1 = sC2[c0 + 1], w2 = sC2[c0 + 2], w3 = sC2[c0 + 3];
    float cb2s = sCB2;

    for (int tile = blockIdx.x; tile < EDGE_TILES; tile += gridDim.x) {
        int e0 = tile * 64 + (tid >> 3) * 4;

        int4 iv = *(const int4*)&ei[e0];
        int4 jv = *(const int4*)&ei[E_EDGES + e0];

        int eq = q & 3;
        int i_own = (eq & 2) ? ((eq & 1) ? iv.w : iv.z) : ((eq & 1) ? iv.y : iv.x);
        int j_own = (eq & 2) ? ((eq & 1) ? jv.w : jv.z) : ((eq & 1) ? jv.y : jv.x);
        float4 pi = g_pos4[i_own], pj = g_pos4[j_own];
        float dx = pi.x - pj.x, dy = pi.y - pj.y, dz = pi.z - pj.z;
        float dist = sqrtf(dx * dx + dy * dy + dz * dz);
        float u = fminf(dist, D_CUT) * ((float)(TAB - 1) / D_CUT);
        int i0_own = min((int)(u + 0.5f), TAB - 1);

        int i0A = __shfl_sync(0xffffffffu, i0_own, 0, 8);
        int i0B = __shfl_sync(0xffffffffu, i0_own, 1, 8);
        int i0C = __shfl_sync(0xffffffffu, i0_own, 2, 8);
        int i0D = __shfl_sync(0xffffffffu, i0_own, 3, 8);

        float hA[4], egA[4], hB[4], egB[4], hC[4], egC[4], hD[4], egD[4];
        {
            float4 a = *(const float4*)&g_a[iv.x * 32 + c0];
            float4 b = *(const float4*)&g_b[jv.x * 32 + c0];
            float4 t = *(const float4*)&g_tab[i0A * 32 + c0];
            float4 g = *(const float4*)&g_gate[jv.x * 32 + c0];
            hA[0] = siluf(a.x + b.x); hA[1] = siluf(a.y + b.y);
            hA[2] = siluf(a.z + b.z); hA[3] = siluf(a.w + b.w);
            egA[0] = t.x * g.x; egA[1] = t.y * g.y;
            egA[2] = t.z * g.z; egA[3] = t.w * g.w;
        }
        {
            float4 a = *(const float4*)&g_a[iv.y * 32 + c0];
            float4 b = *(const float4*)&g_b[jv.y * 32 + c0];
            float4 t = *(const float4*)&g_tab[i0B * 32 + c0];
            float4 g = *(const float4*)&g_gate[jv.y * 32 + c0];
            hB[0] = siluf(a.x + b.x); hB[1] = siluf(a.y + b.y);
            hB[2] = siluf(a.z + b.z); hB[3] = siluf(a.w + b.w);
            egB[0] = t.x * g.x; egB[1] = t.y * g.y;
            egB[2] = t.z * g.z; egB[3] = t.w * g.w;
        }
        {
            float4 a = *(const float4*)&g_a[iv.z * 32 + c0];
            float4 b = *(const float4*)&g_b[jv.z * 32 + c0];
            float4 t = *(const float4*)&g_tab[i0C * 32 + c0];
            float4 g = *(const float4*)&g_gate[jv.z * 32 + c0];
            hC[0] = siluf(a.x + b.x); hC[1] = siluf(a.y + b.y);
            hC[2] = siluf(a.z + b.z); hC[3] = siluf(a.w + b.w);
            egC[0] = t.x * g.x; egC[1] = t.y * g.y;
            egC[2] = t.z * g.z; egC[3] = t.w * g.w;
        }
        {
            float4 a = *(const float4*)&g_a[iv.w * 32 + c0];
            float4 b = *(const float4*)&g_b[jv.w * 32 + c0];
            float4 t = *(const float4*)&g_tab[i0D * 32 + c0];
            float4 g = *(const float4*)&g_gate[jv.w * 32 + c0];
            hD[0] = siluf(a.x + b.x); hD[1] = siluf(a.y + b.y);
            hD[2] = siluf(a.z + b.z); hD[3] = siluf(a.w + b.w);
            egD[0] = t.x * g.x; egD[1] = t.y * g.y;
            egD[2] = t.z * g.z; egD[3] = t.w * g.w;
        }

        u64 mmA[2], mmB[2], mmC[2], mmD[2];
        mmA[0] = mb0; mmA[1] = mb1; mmB[0] = mb0; mmB[1] = mb1;
        mmC[0] = mb0; mmC[1] = mb1; mmD[0] = mb0; mmD[1] = mb1;
        MV32X4(mmA, mmB, mmC, mmD, hA, hB, hC, hD, sW2, c0);

        float mA[4], mB[4], mC[4], mD[4];
        {
            float t0, t1;
            unpack2(mmA[0], t0, t1); mA[0] = siluf(t0) * egA[0]; mA[1] = siluf(t1) * egA[1];
            unpack2(mmA[1], t0, t1); mA[2] = siluf(t0) * egA[2]; mA[3] = siluf(t1) * egA[3];
            unpack2(mmB[0], t0, t1); mB[0] = siluf(t0) * egB[0]; mB[1] = siluf(t1) * egB[1];
            unpack2(mmB[1], t0, t1); mB[2] = siluf(t0) * egB[2]; mB[3] = siluf(t1) * egB[3];
            unpack2(mmC[0], t0, t1); mC[0] = siluf(t0) * egC[0]; mC[1] = siluf(t1) * egC[1];
            unpack2(mmC[1], t0, t1); mC[2] = siluf(t0) * egC[2]; mC[3] = siluf(t1) * egC[3];
            unpack2(mmD[0], t0, t1); mD[0] = siluf(t0) * egD[0]; mD[1] = siluf(t1) * egD[1];
            unpack2(mmD[1], t0, t1); mD[2] = siluf(t0) * egD[2]; mD[3] = siluf(t1) * egD[3];
        }

        red_v4(&g_macc[jv.x * 32 + c0], mA[0], mA[1], mA[2], mA[3]);
        red_v4(&g_macc[jv.y * 32 + c0], mB[0], mB[1], mB[2], mB[3]);
        red_v4(&g_macc[jv.z * 32 + c0], mC[0], mC[1], mC[2], mC[3]);
        red_v4(&g_macc[jv.w * 32 + c0], mD[0], mD[1], mD[2], mD[3]);

        u64 stA[2], stB[2], stC[2], stD[2];
        stA[0] = cb0; stA[1] = cb1v; stB[0] = cb0; stB[1] = cb1v;
        stC[0] = cb0; stC[1] = cb1v; stD[0] = cb0; stD[1] = cb1v;
        MV32X4(stA, stB, stC, stD, mA, mB, mC, mD, sC1, c0);

        float spA, spB, spC, spD;
        {
            float t0, t1, t2, t3;
            unpack2(stA[0], t0, t1); unpack2(stA[1], t2, t3);
            spA = siluf(t0) * w0 + siluf(t1) * w1 + siluf(t2) * w2 + siluf(t3) * w3;
            unpack2(stB[0], t0, t1); unpack2(stB[1], t2, t3);
            spB = siluf(t0) * w0 + siluf(t1) * w1 + siluf(t2) * w2 + siluf(t3) * w3;
            unpack2(stC[0], t0, t1); unpack2(stC[1], t2, t3);
            spC = siluf(t0) * w0 + siluf(t1) * w1 + siluf(t2) * w2 + siluf(t3) * w3;
            unpack2(stD[0], t0, t1); unpack2(stD[1], t2, t3);
            spD = siluf(t0) * w0 + siluf(t1) * w1 + siluf(t2) * w2 + siluf(t3) * w3;
        }
        spA += __shfl_xor_sync(0xffffffffu, spA, 1);
        spA += __shfl_xor_sync(0xffffffffu, spA, 2);
        spA += __shfl_xor_sync(0xffffffffu, spA, 4);
        spB += __shfl_xor_sync(0xffffffffu, spB, 1);
        spB += __shfl_xor_sync(0xffffffffu, spB, 2);
        spB += __shfl_xor_sync(0xffffffffu, spB, 4);
        spC += __shfl_xor_sync(0xffffffffu, spC, 1);
        spC += __shfl_xor_sync(0xffffffffu, spC, 2);
        spC += __shfl_xor_sync(0xffffffffu, spC, 4);
        spD += __shfl_xor_sync(0xffffffffu, spD, 1);
        spD += __shfl_xor_sync(0xffffffffu, spD, 2);
        spD += __shfl_xor_sync(0xffffffffu, spD, 4);

        if (q < 4) {
            float s_own = (q & 2) ? ((q & 1) ? spD : spC) : ((q & 1) ? spB : spA);
            s_own += cb2s;
            red_v4(&g_pacc[j_own * 4], dx * s_own, dy * s_own, dz * s_own, 1.0f);
        }
    }
}

// ---------------- K4: combine + outputs, persistent, 8 lanes x NE=4 ---------
__global__ void __launch_bounds__(128) k_final(
        const float* __restrict__ pos,
        const float* __restrict__ comb_w1, const float* __restrict__ cb1,
        const float* __restrict__ comb_w2, const float* __restrict__ cb2,
        float* __restrict__ outx, float* __restrict__ outp) {
    __shared__ __align__(16) float sW1[64 * 32];
    __shared__ __align__(16) float sW2[32 * 32];
    int tid = threadIdx.x;
    for (int k = tid; k < 2048; k += 128) sW1[k] = comb_w1[k];
    for (int k = tid; k < 1024; k += 128) sW2[k] = comb_w2[k];
    __syncthreads();

    int q = tid & 7;
    int c0 = q * 4;
    int half = (q & 3) * 8;

    u64 b1p0 = pack2(cb1[c0], cb1[c0 + 1]);
    u64 b1p1 = pack2(cb1[c0 + 2], cb1[c0 + 3]);
    u64 b2p0 = pack2(cb2[c0], cb2[c0 + 1]);
    u64 b2p1 = pack2(cb2[c0 + 2], cb2[c0 + 3]);

    for (int tile = blockIdx.x; tile < NODE_TILES; tile += gridDim.x) {
        int n0 = tile * 64 + (tid >> 3) * 4;
        if (n0 >= N_NODES) continue;   // warp-uniform

        float inA[8], inB[8], inC[8], inD[8];
        {
            const float* src = (q < 4) ? &g_xm[n0 * 32] : &g_macc[n0 * 32];
            float4 v0 = *(const float4*)&src[half];
            float4 v1 = *(const float4*)&src[half + 4];
            inA[0] = v0.x; inA[1] = v0.y; inA[2] = v0.z; inA[3] = v0.w;
            inA[4] = v1.x; inA[5] = v1.y; inA[6] = v1.z; inA[7] = v1.w;
        }
        {
            const float* src = (q < 4) ? &g_xm[(n0 + 1) * 32] : &g_macc[(n0 + 1) * 32];
            float4 v0 = *(const float4*)&src[half];
            float4 v1 = *(const float4*)&src[half + 4];
            inB[0] = v0.x; inB[1] = v0.y; inB[2] = v0.z; inB[3] = v0.w;
            inB[4] = v1.x; inB[5] = v1.y; inB[6] = v1.z; inB[7] = v1.w;
        }
        {
            const float* src = (q < 4) ? &g_xm[(n0 + 2) * 32] : &g_macc[(n0 + 2) * 32];
            float4 v0 = *(const float4*)&src[half];
            float4 v1 = *(const float4*)&src[half + 4];
            inC[0] = v0.x; inC[1] = v0.y; inC[2] = v0.z; inC[3] = v0.w;
            inC[4] = v1.x; inC[5] = v1.y; inC[6] = v1.z; inC[7] = v1.w;
        }
        {
            const float* src = (q < 4) ? &g_xm[(n0 + 3) * 32] : &g_macc[(n0 + 3) * 32];
            float4 v0 = *(const float4*)&src[half];
            float4 v1 = *(const float4*)&src[half + 4];
            inD[0] = v0.x; inD[1] = v0.y; inD[2] = v0.z; inD[3] = v0.w;
            inD[4] = v1.x; inD[5] = v1.y; inD[6] = v1.z; inD[7] = v1.w;
        }

        u64 accA[2], accB[2], accC[2], accD[2];
        accA[0] = b1p0; accA[1] = b1p1; accB[0] = b1p0; accB[1] = b1p1;
        accC[0] = b1p0; accC[1] = b1p1; accD[0] = b1p0; accD[1] = b1p1;
        #pragma unroll
        for (int kk = 0; kk < 64; kk++) {
            float vA = __shfl_sync(0xffffffffu, inA[kk & 7], kk >> 3, 8);
            float vB = __shfl_sync(0xffffffffu, inB[kk & 7], kk >> 3, 8);
            float vC = __shfl_sync(0xffffffffu, inC[kk & 7], kk >> 3, 8);
            float vD = __shfl_sync(0xffffffffu, inD[kk & 7], kk >> 3, 8);
            u64 vvA = pack2(vA, vA), vvB = pack2(vB, vB);
            u64 vvC = pack2(vC, vC), vvD = pack2(vD, vD);
            ulonglong2 w = *(const ulonglong2*)&sW1[kk * 32 + c0];
            ffma2(accA[0], w.x, vvA); ffma2(accA[1], w.y, vvA);
            ffma2(accB[0], w.x, vvB); ffma2(accB[1], w.y, vvB);
            ffma2(accC[0], w.x, vvC); ffma2(accC[1], w.y, vvC);
            ffma2(accD[0], w.x, vvD); ffma2(accD[1], w.y, vvD);
        }
        float hhA[4], hhB[4], hhC[4], hhD[4];
        {
            float t0, t1;
            unpack2(accA[0], t0, t1); hhA[0] = siluf(t0); hhA[1] = siluf(t1);
            unpack2(accA[1], t0, t1); hhA[2] = siluf(t0); hhA[3] = siluf(t1);
            unpack2(accB[0], t0, t1); hhB[0] = siluf(t0); hhB[1] = siluf(t1);
            unpack2(accB[1], t0, t1); hhB[2] = siluf(t0); hhB[3] = siluf(t1);
            unpack2(accC[0], t0, t1); hhC[0] = siluf(t0); hhC[1] = siluf(t1);
            unpack2(accC[1], t0, t1); hhC[2] = siluf(t0); hhC[3] = siluf(t1);
            unpack2(accD[0], t0, t1); hhD[0] = siluf(t0); hhD[1] = siluf(t1);
            unpack2(accD[1], t0, t1); hhD[2] = siluf(t0); hhD[3] = siluf(t1);
        }

        u64 a2A[2], a2B[2], a2C[2], a2D[2];
        a2A[0] = b2p0; a2A[1] = b2p1; a2B[0] = b2p0; a2B[1] = b2p1;
        a2C[0] = b2p0; a2C[1] = b2p1; a2D[0] = b2p0; a2D[1] = b2p1;
        MV32X4(a2A, a2B, a2C, a2D, hhA, hhB, hhC, hhD, sW2, c0);

        {
            float t0, t1, t2, t3;
            unpack2(a2A[0], t0, t1); unpack2(a2A[1], t2, t3);
            float4 xm = *(const float4*)&g_xm[n0 * 32 + c0];
            *(float4*)&outx[n0 * 32 + c0] = make_float4(
                siluf(xm.x + t0), siluf(xm.y + t1), siluf(xm.z + t2), siluf(xm.w + t3));
        }
        {
            int n = n0 + 1;
            float t0, t1, t2, t3;
            unpack2(a2B[0], t0, t1); unpack2(a2B[1], t2, t3);
            float4 xm = *(const float4*)&g_xm[n * 32 + c0];
            *(float4*)&outx[n * 32 + c0] = make_float4(
                siluf(xm.x + t0), siluf(xm.y + t1), siluf(xm.z + t2), siluf(xm.w + t3));
        }
        {
            int n = n0 + 2;
            float t0, t1, t2, t3;
            unpack2(a2C[0], t0, t1); unpack2(a2C[1], t2, t3);
            float4 xm = *(const float4*)&g_xm[n * 32 + c0];
            *(float4*)&outx[n * 32 + c0] = make_float4(
                siluf(xm.x + t0), siluf(xm.y + t1), siluf(xm.z + t2), siluf(xm.w + t3));
        }
        {
            int n = n0 + 3;
            float t0, t1, t2, t3;
            unpack2(a2D[0], t0, t1); unpack2(a2D[1], t2, t3);
            float4 xm = *(const float4*)&g_xm[n * 32 + c0];
            *(float4*)&outx[n * 32 + c0] = make_float4(
                siluf(xm.x + t0), siluf(xm.y + t1), siluf(xm.z + t2), siluf(xm.w + t3));
        }

        if (q < 4) {
            int n = n0 + q;
            float4 pa = *(const float4*)&g_pacc[n * 4];
            float ic = 1.0f / fmaxf(pa.w, 1.0f);
            outp[n * 3 + 0] = pos[n * 3 + 0] + pa.x * ic;
            outp[n * 3 + 1] = pos[n * 3 + 1] + pa.y * ic;
            outp[n * 3 + 2] = pos[n * 3 + 2] + pa.z * ic;
        }
    }
}

// ---------------- launch ----------------
static int s_sm_count = 0;
static int s_blk_edge = 0, s_blk_node = 0, s_blk_final = 0;

extern "C" void kernel_launch(void* const* d_in, const int* in_sizes, int n_in,
                              void* d_out, int out_size) {
    const float* x        = (const float*)d_in[0];
    const int*   ei       = (const int*)d_in[1];
    const float* pos      = (const float*)d_in[2];
    const float* time     = (const float*)d_in[3];
    const int*   batch    = (const int*)d_in[4];
    const float* means    = (const float*)d_in[5];
    const float* betas    = (const float*)d_in[6];
    const float* w_dist   = (const float*)d_in[7];
    const float* msg_w1   = (const float*)d_in[8];
    const float* msg_b1   = (const float*)d_in[9];
    const float* msg_w2   = (const float*)d_in[10];
    const float* msg_b2   = (const float*)d_in[11];
    const float* gate_w   = (const float*)d_in[12];
    const float* gate_b   = (const float*)d_in[13];
    const float* time_w1  = (const float*)d_in[14];
    const float* time_b1  = (const float*)d_in[15];
    const float* time_w2  = (const float*)d_in[16];
    const float* time_b2  = (const float*)d_in[17];
    const float* comb_w1  = (const float*)d_in[18];
    const float* comb_b1  = (const float*)d_in[19];
    const float* comb_w2  = (const float*)d_in[20];
    const float* comb_b2  = (const float*)d_in[21];
    const float* coord_w1 = (const float*)d_in[22];
    const float* coord_b1 = (const float*)d_in[23];
    const float* coord_w2 = (const float*)d_in[24];
    const float* coord_b2 = (const float*)d_in[25];

    float* outx = (float*)d_out;
    float* outp = (float*)d_out + N_NODES * 32;

    if (s_sm_count == 0) {
        cudaDeviceGetAttribute(&s_sm_count, cudaDevAttrMultiProcessorCount, 0);
        int b;
        cudaOccupancyMaxActiveBlocksPerMultiprocessor(&b, k_edge, 128, 0);
        s_blk_edge = b > 0 ? b : 4;
        cudaOccupancyMaxActiveBlocksPerMultiprocessor(&b, k_node, 128, 0);
        s_blk_node = b > 0 ? b : 4;
        cudaOccupancyMaxActiveBlocksPerMultiprocessor(&b, k_final, 128, 0);
        s_blk_final = b > 0 ? b : 4;
    }
    int ge = s_sm_count * s_blk_edge;   if (ge > EDGE_TILES) ge = EDGE_TILES;
    int gn = s_sm_count * s_blk_node;   if (gn > NODE_TILES) gn = NODE_TILES;
    int gf = s_sm_count * s_blk_final;  if (gf > NODE_TILES) gf = NODE_TILES;

    k_time<<<G_GRAPHS / 4 + TAB / 8, 256>>>(time, time_w1, time_b1, time_w2, time_b2,
                                            means, betas, w_dist);
    k_node<<<gn, 128>>>(x, batch, pos, msg_w1, msg_b1, gate_w, gate_b);
    k_edge<<<ge, 128>>>(ei, msg_w2, msg_b2,
                        coord_w1, coord_b1, coord_w2, coord_b2);
    k_final<<<gf, 128>>>(pos, comb_w1, comb_b1, comb_w2, comb_b2,
                         outx, outp);
}

// round 14
// speedup vs baseline: 1.5887x; 1.1197x over previous
#include <cuda_runtime.h>
#include <math.h>

#define N_NODES 100000
#define E_EDGES 800000
#define G_GRAPHS 512
#define HID 32
#define D_CUT 5.0f
#define TAB 8192
#define NODE_BLOCKS 1563  // ceil(100000/64)
#define EDGE_TILES 12500  // 800000/64

typedef unsigned long long u64;

// ---------------- scratch (static, no allocation) ----------------
__device__ __align__(16) float g_ss[G_GRAPHS * 64];
__device__ __align__(16) float g_xm[N_NODES * 32];
__device__ __align__(16) float g_a[N_NODES * 32];
__device__ __align__(16) float g_b[N_NODES * 32];
__device__ __align__(16) float g_gate[N_NODES * 32];
__device__ __align__(16) float g_macc[N_NODES * 32];
__device__ __align__(16) float g_pacc[N_NODES * 4];
__device__ __align__(16) float4 g_pos4[N_NODES];
__device__ __align__(16) float g_tab[TAB * 32];

// tanh-based activations: 1 MUFU + 2 FFMA (vs EX2+RCP+div fixup)
__device__ __forceinline__ float tanha(float x) {
    float y; asm("tanh.approx.f32 %0, %1;" : "=f"(y) : "f"(x)); return y;
}
__device__ __forceinline__ float siluf(float v) {
    return v * (0.5f * tanha(0.5f * v) + 0.5f);
}
__device__ __forceinline__ float sigmf(float v) {
    return 0.5f * tanha(0.5f * v) + 0.5f;
}
// precise versions for the precomputed table / time MLP (cheap, run once)
__device__ __forceinline__ float siluf_p(float v) { return v / (1.0f + __expf(-v)); }

__device__ __forceinline__ void red_v4(float* p, float a, float b, float c, float d) {
    asm volatile("red.global.add.v4.f32 [%0], {%1,%2,%3,%4};"
                 :: "l"(p), "f"(a), "f"(b), "f"(c), "f"(d) : "memory");
}

__device__ __forceinline__ u64 pack2(float lo, float hi) {
    u64 r; asm("mov.b64 %0, {%1, %2};" : "=l"(r) : "f"(lo), "f"(hi)); return r;
}
__device__ __forceinline__ void unpack2(u64 v, float& lo, float& hi) {
    asm("mov.b64 {%0, %1}, %2;" : "=f"(lo), "=f"(hi) : "l"(v));
}
__device__ __forceinline__ void ffma2(u64& d, u64 a, u64 b) {
    asm("fma.rn.f32x2 %0, %1, %2, %0;" : "+l"(d) : "l"(a), "l"(b));
}

// ---------------- K1: time MLP + dist_emb table (fused) ----------------
__global__ void __launch_bounds__(256) k_time(
        const float* __restrict__ time,
        const float* __restrict__ w1, const float* __restrict__ b1,
        const float* __restrict__ w2, const float* __restrict__ b2,
        const float* __restrict__ means, const float* __restrict__ betas,
        const float* __restrict__ w_dist) {
    int tid = threadIdx.x;
    if (blockIdx.x >= G_GRAPHS / 4) {
        __shared__ float sW[1024];
        __shared__ float sMu[32], sBeta[32];
        for (int k = tid; k < 1024; k += 256) sW[k] = w_dist[k];
        if (tid < 32) { sMu[tid] = means[tid]; sBeta[tid] = betas[tid]; }
        __syncthreads();
        int r = (blockIdx.x - G_GRAPHS / 4) * 8 + (tid >> 5);
        int c = tid & 31;
        float d = (float)r * (D_CUT / (float)(TAB - 1));
        float cutoff = 0.5f * (__cosf(d * (3.14159265358979f / D_CUT)) + 1.0f);
        float ed = __expf(-d);
        float acc = 0.0f;
        #pragma unroll 8
        for (int k = 0; k < 32; k++) {
            float t = ed - sMu[k];
            acc += __expf(-sBeta[k] * t * t) * sW[k * 32 + c];
        }
        g_tab[r * 32 + c] = cutoff * acc;
        return;
    }
    __shared__ float trow[4][128];
    __shared__ float hid[4][64];
    int gsub = tid >> 6;
    int t = tid & 63;
    int g = blockIdx.x * 4 + gsub;
    trow[gsub][t]      = time[g * 128 + t];
    trow[gsub][t + 64] = time[g * 128 + 64 + t];
    __syncthreads();
    float acc = b1[t];
    #pragma unroll 8
    for (int k = 0; k < 128; k++) acc += trow[gsub][k] * w1[k * 64 + t];
    hid[gsub][t] = siluf_p(acc);
    __syncthreads();
    float acc2 = b2[t];
    #pragma unroll 8
    for (int k = 0; k < 64; k++) acc2 += hid[gsub][k] * w2[k * 64 + t];
    g_ss[g * 64 + t] = acc2;
}

// ---------------- K2: per-node precompute, 8 lanes x NE=4 (non-persistent) --
__global__ void __launch_bounds__(128) k_node(
        const float* __restrict__ x, const int* __restrict__ batch,
        const float* __restrict__ pos,
        const float* __restrict__ msg_w1, const float* __restrict__ msg_b1,
        const float* __restrict__ gate_w, const float* __restrict__ gate_b) {
    __shared__ __align__(16) float sW1[64 * 32];
    __shared__ __align__(16) float sWg[32 * 32];
    int tid = threadIdx.x;
    for (int k = tid; k < 2048; k += 128) sW1[k] = msg_w1[k];
    for (int k = tid; k < 1024; k += 128) sWg[k] = gate_w[k];
    __syncthreads();

    int q = tid & 7;
    int c0 = q * 4;
    int n0 = blockIdx.x * 64 + (tid >> 3) * 4;
    if (n0 >= N_NODES) return;   // warp-uniform: 16 nodes/warp, 16 | 100000

    float xmA[4], xmB[4], xmC[4], xmD[4];
    {
        int bn = batch[n0];
        float4 sc = *(const float4*)&g_ss[bn * 64 + c0];
        float4 sh = *(const float4*)&g_ss[bn * 64 + 32 + c0];
        float4 xv = *(const float4*)&x[n0 * 32 + c0];
        xmA[0] = siluf(xv.x * (1.0f + sc.x) + sh.x);
        xmA[1] = siluf(xv.y * (1.0f + sc.y) + sh.y);
        xmA[2] = siluf(xv.z * (1.0f + sc.z) + sh.z);
        xmA[3] = siluf(xv.w * (1.0f + sc.w) + sh.w);
    }
    {
        int bn = batch[n0 + 1];
        float4 sc = *(const float4*)&g_ss[bn * 64 + c0];
        float4 sh = *(const float4*)&g_ss[bn * 64 + 32 + c0];
        float4 xv = *(const float4*)&x[(n0 + 1) * 32 + c0];
        xmB[0] = siluf(xv.x * (1.0f + sc.x) + sh.x);
        xmB[1] = siluf(xv.y * (1.0f + sc.y) + sh.y);
        xmB[2] = siluf(xv.z * (1.0f + sc.z) + sh.z);
        xmB[3] = siluf(xv.w * (1.0f + sc.w) + sh.w);
    }
    {
        int bn = batch[n0 + 2];
        float4 sc = *(const float4*)&g_ss[bn * 64 + c0];
        float4 sh = *(const float4*)&g_ss[bn * 64 + 32 + c0];
        float4 xv = *(const float4*)&x[(n0 + 2) * 32 + c0];
        xmC[0] = siluf(xv.x * (1.0f + sc.x) + sh.x);
        xmC[1] = siluf(xv.y * (1.0f + sc.y) + sh.y);
        xmC[2] = siluf(xv.z * (1.0f + sc.z) + sh.z);
        xmC[3] = siluf(xv.w * (1.0f + sc.w) + sh.w);
    }
    {
        int bn = batch[n0 + 3];
        float4 sc = *(const float4*)&g_ss[bn * 64 + c0];
        float4 sh = *(const float4*)&g_ss[bn * 64 + 32 + c0];
        float4 xv = *(const float4*)&x[(n0 + 3) * 32 + c0];
        xmD[0] = siluf(xv.x * (1.0f + sc.x) + sh.x);
        xmD[1] = siluf(xv.y * (1.0f + sc.y) + sh.y);
        xmD[2] = siluf(xv.z * (1.0f + sc.z) + sh.z);
        xmD[3] = siluf(xv.w * (1.0f + sc.w) + sh.w);
    }

    u64 aA[2], aB[2], aC[2], aD[2];
    u64 bA[2], bB[2], bC[2], bD[2];
    u64 gA[2], gB[2], gC[2], gD[2];
    {
        u64 m0 = pack2(msg_b1[c0], msg_b1[c0 + 1]);
        u64 m1 = pack2(msg_b1[c0 + 2], msg_b1[c0 + 3]);
        u64 g0 = pack2(gate_b[c0], gate_b[c0 + 1]);
        u64 g1 = pack2(gate_b[c0 + 2], gate_b[c0 + 3]);
        aA[0] = m0; aA[1] = m1; aB[0] = m0; aB[1] = m1;
        aC[0] = m0; aC[1] = m1; aD[0] = m0; aD[1] = m1;
        bA[0] = 0; bA[1] = 0; bB[0] = 0; bB[1] = 0;
        bC[0] = 0; bC[1] = 0; bD[0] = 0; bD[1] = 0;
        gA[0] = g0; gA[1] = g1; gB[0] = g0; gB[1] = g1;
        gC[0] = g0; gC[1] = g1; gD[0] = g0; gD[1] = g1;
    }
    #pragma unroll
    for (int kk = 0; kk < 32; kk++) {
        float vA = __shfl_sync(0xffffffffu, xmA[kk & 3], kk >> 2, 8);
        float vB = __shfl_sync(0xffffffffu, xmB[kk & 3], kk >> 2, 8);
        float vC = __shfl_sync(0xffffffffu, xmC[kk & 3], kk >> 2, 8);
        float vD = __shfl_sync(0xffffffffu, xmD[kk & 3], kk >> 2, 8);
        u64 vvA = pack2(vA, vA), vvB = pack2(vB, vB);
        u64 vvC = pack2(vC, vC), vvD = pack2(vD, vD);
        ulonglong2 wa = *(const ulonglong2*)&sW1[kk * 32 + c0];
        ulonglong2 wb = *(const ulonglong2*)&sW1[(32 + kk) * 32 + c0];
        ulonglong2 wg = *(const ulonglong2*)&sWg[kk * 32 + c0];
        ffma2(aA[0], wa.x, vvA); ffma2(aA[1], wa.y, vvA);
        ffma2(aB[0], wa.x, vvB); ffma2(aB[1], wa.y, vvB);
        ffma2(aC[0], wa.x, vvC); ffma2(aC[1], wa.y, vvC);
        ffma2(aD[0], wa.x, vvD); ffma2(aD[1], wa.y, vvD);
        ffma2(bA[0], wb.x, vvA); ffma2(bA[1], wb.y, vvA);
        ffma2(bB[0], wb.x, vvB); ffma2(bB[1], wb.y, vvB);
        ffma2(bC[0], wb.x, vvC); ffma2(bC[1], wb.y, vvC);
        ffma2(bD[0], wb.x, vvD); ffma2(bD[1], wb.y, vvD);
        ffma2(gA[0], wg.x, vvA); ffma2(gA[1], wg.y, vvA);
        ffma2(gB[0], wg.x, vvB); ffma2(gB[1], wg.y, vvB);
        ffma2(gC[0], wg.x, vvC); ffma2(gC[1], wg.y, vvC);
        ffma2(gD[0], wg.x, vvD); ffma2(gD[1], wg.y, vvD);
    }

    float4 z = make_float4(0.f, 0.f, 0.f, 0.f);
    {
        *(float4*)&g_xm[n0 * 32 + c0] = make_float4(xmA[0], xmA[1], xmA[2], xmA[3]);
        *(ulonglong2*)&g_a[n0 * 32 + c0] = make_ulonglong2(aA[0], aA[1]);
        *(ulonglong2*)&g_b[n0 * 32 + c0] = make_ulonglong2(bA[0], bA[1]);
        float t0, t1, t2, t3;
        unpack2(gA[0], t0, t1); unpack2(gA[1], t2, t3);
        *(float4*)&g_gate[n0 * 32 + c0] =
            make_float4(sigmf(t0), sigmf(t1), sigmf(t2), sigmf(t3));
        *(float4*)&g_macc[n0 * 32 + c0] = z;
    }
    {
        int n = n0 + 1;
        *(float4*)&g_xm[n * 32 + c0] = make_float4(xmB[0], xmB[1], xmB[2], xmB[3]);
        *(ulonglong2*)&g_a[n * 32 + c0] = make_ulonglong2(aB[0], aB[1]);
        *(ulonglong2*)&g_b[n * 32 + c0] = make_ulonglong2(bB[0], bB[1]);
        float t0, t1, t2, t3;
        unpack2(gB[0], t0, t1); unpack2(gB[1], t2, t3);
        *(float4*)&g_gate[n * 32 + c0] =
            make_float4(sigmf(t0), sigmf(t1), sigmf(t2), sigmf(t3));
        *(float4*)&g_macc[n * 32 + c0] = z;
    }
    {
        int n = n0 + 2;
        *(float4*)&g_xm[n * 32 + c0] = make_float4(xmC[0], xmC[1], xmC[2], xmC[3]);
        *(ulonglong2*)&g_a[n * 32 + c0] = make_ulonglong2(aC[0], aC[1]);
        *(ulonglong2*)&g_b[n * 32 + c0] = make_ulonglong2(bC[0], bC[1]);
        float t0, t1, t2, t3;
        unpack2(gC[0], t0, t1); unpack2(gC[1], t2, t3);
        *(float4*)&g_gate[n * 32 + c0] =
            make_float4(sigmf(t0), sigmf(t1), sigmf(t2), sigmf(t3));
        *(float4*)&g_macc[n * 32 + c0] = z;
    }
    {
        int n = n0 + 3;
        *(float4*)&g_xm[n * 32 + c0] = make_float4(xmD[0], xmD[1], xmD[2], xmD[3]);
        *(ulonglong2*)&g_a[n * 32 + c0] = make_ulonglong2(aD[0], aD[1]);
        *(ulonglong2*)&g_b[n * 32 + c0] = make_ulonglong2(bD[0], bD[1]);
        float t0, t1, t2, t3;
        unpack2(gD[0], t0, t1); unpack2(gD[1], t2, t3);
        *(float4*)&g_gate[n * 32 + c0] =
            make_float4(sigmf(t0), sigmf(t1), sigmf(t2), sigmf(t3));
        *(float4*)&g_macc[n * 32 + c0] = z;
    }
    if (q < 4) {
        int n = n0 + q;
        *(float4*)&g_pacc[n * 4] = z;
        g_pos4[n] = make_float4(pos[n * 3], pos[n * 3 + 1], pos[n * 3 + 2], 0.0f);
    }
}

// ---------------- K3: edge kernel, persistent, 8 lanes/group x NE=4 ---------
#define MV32X4(aA, aB, aC, aD, iA_, iB_, iC_, iD_, W, c0)                        \
    do {                                                                         \
        _Pragma("unroll")                                                        \
        for (int kk = 0; kk < 32; kk++) {                                        \
            float vA = __shfl_sync(0xffffffffu, iA_[kk & 3], kk >> 2, 8);        \
            float vB = __shfl_sync(0xffffffffu, iB_[kk & 3], kk >> 2, 8);        \
            float vC = __shfl_sync(0xffffffffu, iC_[kk & 3], kk >> 2, 8);        \
            float vD = __shfl_sync(0xffffffffu, iD_[kk & 3], kk >> 2, 8);        \
            u64 vvA = pack2(vA, vA), vvB = pack2(vB, vB);                        \
            u64 vvC = pack2(vC, vC), vvD = pack2(vD, vD);                        \
            ulonglong2 w = *(const ulonglong2*)&W[kk * 32 + c0];                 \
            ffma2(aA[0], w.x, vvA); ffma2(aA[1], w.y, vvA);                      \
            ffma2(aB[0], w.x, vvB); ffma2(aB[1], w.y, vvB);                      \
            ffma2(aC[0], w.x, vvC); ffma2(aC[1], w.y, vvC);                      \
            ffma2(aD[0], w.x, vvD); ffma2(aD[1], w.y, vvD);                      \
        }                                                                        \
    } while (0)

__global__ void __launch_bounds__(128) k_edge(
        const int* __restrict__ ei,
        const float* __restrict__ msg_w2, const float* __restrict__ msg_b2,
        const float* __restrict__ coord_w1, const float* __restrict__ coord_b1,
        const float* __restrict__ coord_w2, const float* __restrict__ coord_b2) {
    __shared__ __align__(16) float sW2[1024];
    __shared__ __align__(16) float sC1[1024];
    __shared__ float sC2[32], sB2[32], sCB1[32];
    __shared__ float sCB2;

    int tid = threadIdx.x;
    for (int k = tid; k < 1024; k += 128) {
        sW2[k] = msg_w2[k];
        sC1[k] = coord_w1[k];
    }
    if (tid < 32) {
        sC2[tid]  = coord_w2[tid];
        sB2[tid]  = msg_b2[tid];
        sCB1[tid] = coord_b1[tid];
    }
    if (tid == 0) sCB2 = coord_b2[0];
    __syncthreads();

    int q = tid & 7;
    int c0 = q * 4;

    u64 mb0 = pack2(sB2[c0], sB2[c0 + 1]);
    u64 mb1 = pack2(sB2[c0 + 2], sB2[c0 + 3]);
    u64 cb0 = pack2(sCB1[c0], sCB1[c0 + 1]);
    u64 cb1v = pack2(sCB1[c0 + 2], sCB1[c0 + 3]);
    float w0 = sC2[c0], w1 = sC2[c0 + 1], w2 = sC2[c0 + 2], w3 = sC2[c0 + 3];
    float cb2s = sCB2;

    for (int tile = blockIdx.x; tile < EDGE_TILES; tile += gridDim.x) {
        int e0 = tile * 64 + (tid >> 3) * 4;

        int4 iv = *(const int4*)&ei[e0];
        int4 jv = *(const int4*)&ei[E_EDGES + e0];

        int eq = q & 3;
        int i_own = (eq & 2) ? ((eq & 1) ? iv.w : iv.z) : ((eq & 1) ? iv.y : iv.x);
        int j_own = (eq & 2) ? ((eq & 1) ? jv.w : jv.z) : ((eq & 1) ? jv.y : jv.x);
        float4 pi = g_pos4[i_own], pj = g_pos4[j_own];
        float dx = pi.x - pj.x, dy = pi.y - pj.y, dz = pi.z - pj.z;
        float dist = sqrtf(dx * dx + dy * dy + dz * dz);
        float u = fminf(dist, D_CUT) * ((float)(TAB - 1) / D_CUT);
        int i0_own = min((int)(u + 0.5f), TAB - 1);

        int i0A = __shfl_sync(0xffffffffu, i0_own, 0, 8);
        int i0B = __shfl_sync(0xffffffffu, i0_own, 1, 8);
        int i0C = __shfl_sync(0xffffffffu, i0_own, 2, 8);
        int i0D = __shfl_sync(0xffffffffu, i0_own, 3, 8);

        float hA[4], egA[4], hB[4], egB[4], hC[4], egC[4], hD[4], egD[4];
        {
            float4 a = *(const float4*)&g_a[iv.x * 32 + c0];
            float4 b = *(const float4*)&g_b[jv.x * 32 + c0];
            float4 t = *(const float4*)&g_tab[i0A * 32 + c0];
            float4 g = *(const float4*)&g_gate[jv.x * 32 + c0];
            hA[0] = siluf(a.x + b.x); hA[1] = siluf(a.y + b.y);
            hA[2] = siluf(a.z + b.z); hA[3] = siluf(a.w + b.w);
            egA[0] = t.x * g.x; egA[1] = t.y * g.y;
            egA[2] = t.z * g.z; egA[3] = t.w * g.w;
        }
        {
            float4 a = *(const float4*)&g_a[iv.y * 32 + c0];
            float4 b = *(const float4*)&g_b[jv.y * 32 + c0];
            float4 t = *(const float4*)&g_tab[i0B * 32 + c0];
            float4 g = *(const float4*)&g_gate[jv.y * 32 + c0];
            hB[0] = siluf(a.x + b.x); hB[1] = siluf(a.y + b.y);
            hB[2] = siluf(a.z + b.z); hB[3] = siluf(a.w + b.w);
            egB[0] = t.x * g.x; egB[1] = t.y * g.y;
            egB[2] = t.z * g.z; egB[3] = t.w * g.w;
        }
        {
            float4 a = *(const float4*)&g_a[iv.z * 32 + c0];
            float4 b = *(const float4*)&g_b[jv.z * 32 + c0];
            float4 t = *(const float4*)&g_tab[i0C * 32 + c0];
            float4 g = *(const float4*)&g_gate[jv.z * 32 + c0];
            hC[0] = siluf(a.x + b.x); hC[1] = siluf(a.y + b.y);
            hC[2] = siluf(a.z + b.z); hC[3] = siluf(a.w + b.w);
            egC[0] = t.x * g.x; egC[1] = t.y * g.y;
            egC[2] = t.z * g.z; egC[3] = t.w * g.w;
        }
        {
            float4 a = *(const float4*)&g_a[iv.w * 32 + c0];
            float4 b = *(const float4*)&g_b[jv.w * 32 + c0];
            float4 t = *(const float4*)&g_tab[i0D * 32 + c0];
            float4 g = *(const float4*)&g_gate[jv.w * 32 + c0];
            hD[0] = siluf(a.x + b.x); hD[1] = siluf(a.y + b.y);
            hD[2] = siluf(a.z + b.z); hD[3] = siluf(a.w + b.w);
            egD[0] = t.x * g.x; egD[1] = t.y * g.y;
            egD[2] = t.z * g.z; egD[3] = t.w * g.w;
        }

        u64 mmA[2], mmB[2], mmC[2], mmD[2];
        mmA[0] = mb0; mmA[1] = mb1; mmB[0] = mb0; mmB[1] = mb1;
        mmC[0] = mb0; mmC[1] = mb1; mmD[0] = mb0; mmD[1] = mb1;
        MV32X4(mmA, mmB, mmC, mmD, hA, hB, hC, hD, sW2, c0);

        float mA[4], mB[4], mC[4], mD[4];
        {
            float t0, t1;
            unpack2(mmA[0], t0, t1); mA[0] = siluf(t0) * egA[0]; mA[1] = siluf(t1) * egA[1];
            unpack2(mmA[1], t0, t1); mA[2] = siluf(t0) * egA[2]; mA[3] = siluf(t1) * egA[3];
            unpack2(mmB[0], t0, t1); mB[0] = siluf(t0) * egB[0]; mB[1] = siluf(t1) * egB[1];
            unpack2(mmB[1], t0, t1); mB[2] = siluf(t0) * egB[2]; mB[3] = siluf(t1) * egB[3];
            unpack2(mmC[0], t0, t1); mC[0] = siluf(t0) * egC[0]; mC[1] = siluf(t1) * egC[1];
            unpack2(mmC[1], t0, t1); mC[2] = siluf(t0) * egC[2]; mC[3] = siluf(t1) * egC[3];
            unpack2(mmD[0], t0, t1); mD[0] = siluf(t0) * egD[0]; mD[1] = siluf(t1) * egD[1];
            unpack2(mmD[1], t0, t1); mD[2] = siluf(t0) * egD[2]; mD[3] = siluf(t1) * egD[3];
        }

        red_v4(&g_macc[jv.x * 32 + c0], mA[0], mA[1], mA[2], mA[3]);
        red_v4(&g_macc[jv.y * 32 + c0], mB[0], mB[1], mB[2], mB[3]);
        red_v4(&g_macc[jv.z * 32 + c0], mC[0], mC[1], mC[2], mC[3]);
        red_v4(&g_macc[jv.w * 32 + c0], mD[0], mD[1], mD[2], mD[3]);

        u64 stA[2], stB[2], stC[2], stD[2];
        stA[0] = cb0; stA[1] = cb1v; stB[0] = cb0; stB[1] = cb1v;
        stC[0] = cb0; stC[1] = cb1v; stD[0] = cb0; stD[1] = cb1v;
        MV32X4(stA, stB, stC, stD, mA, mB, mC, mD, sC1, c0);

        float spA, spB, spC, spD;
        {
            float t0, t1, t2, t3;
            unpack2(stA[0], t0, t1); unpack2(stA[1], t2, t3);
            spA = siluf(t0) * w0 + siluf(t1) * w1 + siluf(t2) * w2 + siluf(t3) * w3;
            unpack2(stB[0], t0, t1); unpack2(stB[1], t2, t3);
            spB = siluf(t0) * w0 + siluf(t1) * w1 + siluf(t2) * w2 + siluf(t3) * w3;
            unpack2(stC[0], t0, t1); unpack2(stC[1], t2, t3);
            spC = siluf(t0) * w0 + siluf(t1) * w1 + siluf(t2) * w2 + siluf(t3) * w3;
            unpack2(stD[0], t0, t1); unpack2(stD[1], t2, t3);
            spD = siluf(t0) * w0 + siluf(t1) * w1 + siluf(t2) * w2 + siluf(t3) * w3;
        }
        spA += __shfl_xor_sync(0xffffffffu, spA, 1);
        spA += __shfl_xor_sync(0xffffffffu, spA, 2);
        spA += __shfl_xor_sync(0xffffffffu, spA, 4);
        spB += __shfl_xor_sync(0xffffffffu, spB, 1);
        spB += __shfl_xor_sync(0xffffffffu, spB, 2);
        spB += __shfl_xor_sync(0xffffffffu, spB, 4);
        spC += __shfl_xor_sync(0xffffffffu, spC, 1);
        spC += __shfl_xor_sync(0xffffffffu, spC, 2);
        spC += __shfl_xor_sync(0xffffffffu, spC, 4);
        spD += __shfl_xor_sync(0xffffffffu, spD, 1);
        spD += __shfl_xor_sync(0xffffffffu, spD, 2);
        spD += __shfl_xor_sync(0xffffffffu, spD, 4);

        if (q < 4) {
            float s_own = (q & 2) ? ((q & 1) ? spD : spC) : ((q & 1) ? spB : spA);
            s_own += cb2s;
            red_v4(&g_pacc[j_own * 4], dx * s_own, dy * s_own, dz * s_own, 1.0f);
        }
    }
}

// ---------------- K4: combine + outputs, 8 lanes x NE=4 (non-persistent) ----
__global__ void __launch_bounds__(128) k_final(
        const float* __restrict__ pos,
        const float* __restrict__ comb_w1, const float* __restrict__ cb1,
        const float* __restrict__ comb_w2, const float* __restrict__ cb2,
        float* __restrict__ outx, float* __restrict__ outp) {
    __shared__ __align__(16) float sW1[64 * 32];
    __shared__ __align__(16) float sW2[32 * 32];
    int tid = threadIdx.x;
    for (int k = tid; k < 2048; k += 128) sW1[k] = comb_w1[k];
    for (int k = tid; k < 1024; k += 128) sW2[k] = comb_w2[k];
    __syncthreads();

    int q = tid & 7;
    int c0 = q * 4;
    int n0 = blockIdx.x * 64 + (tid >> 3) * 4;
    if (n0 >= N_NODES) return;   // warp-uniform
    int half = (q & 3) * 8;

    float inA[8], inB[8], inC[8], inD[8];
    {
        const float* src = (q < 4) ? &g_xm[n0 * 32] : &g_macc[n0 * 32];
        float4 v0 = *(const float4*)&src[half];
        float4 v1 = *(const float4*)&src[half + 4];
        inA[0] = v0.x; inA[1] = v0.y; inA[2] = v0.z; inA[3] = v0.w;
        inA[4] = v1.x; inA[5] = v1.y; inA[6] = v1.z; inA[7] = v1.w;
    }
    {
        const float* src = (q < 4) ? &g_xm[(n0 + 1) * 32] : &g_macc[(n0 + 1) * 32];
        float4 v0 = *(const float4*)&src[half];
        float4 v1 = *(const float4*)&src[half + 4];
        inB[0] = v0.x; inB[1] = v0.y; inB[2] = v0.z; inB[3] = v0.w;
        inB[4] = v1.x; inB[5] = v1.y; inB[6] = v1.z; inB[7] = v1.w;
    }
    {
        const float* src = (q < 4) ? &g_xm[(n0 + 2) * 32] : &g_macc[(n0 + 2) * 32];
        float4 v0 = *(const float4*)&src[half];
        float4 v1 = *(const float4*)&src[half + 4];
        inC[0] = v0.x; inC[1] = v0.y; inC[2] = v0.z; inC[3] = v0.w;
        inC[4] = v1.x; inC[5] = v1.y; inC[6] = v1.z; inC[7] = v1.w;
    }
    {
        const float* src = (q < 4) ? &g_xm[(n0 + 3) * 32] : &g_macc[(n0 + 3) * 32];
        float4 v0 = *(const float4*)&src[half];
        float4 v1 = *(const float4*)&src[half + 4];
        inD[0] = v0.x; inD[1] = v0.y; inD[2] = v0.z; inD[3] = v0.w;
        inD[4] = v1.x; inD[5] = v1.y; inD[6] = v1.z; inD[7] = v1.w;
    }

    u64 accA[2], accB[2], accC[2], accD[2];
    {
        u64 b0 = pack2(cb1[c0], cb1[c0 + 1]);
        u64 b1 = pack2(cb1[c0 + 2], cb1[c0 + 3]);
        accA[0] = b0; accA[1] = b1; accB[0] = b0; accB[1] = b1;
        accC[0] = b0; accC[1] = b1; accD[0] = b0; accD[1] = b1;
    }
    #pragma unroll
    for (int kk = 0; kk < 64; kk++) {
        float vA = __shfl_sync(0xffffffffu, inA[kk & 7], kk >> 3, 8);
        float vB = __shfl_sync(0xffffffffu, inB[kk & 7], kk >> 3, 8);
        float vC = __shfl_sync(0xffffffffu, inC[kk & 7], kk >> 3, 8);
        float vD = __shfl_sync(0xffffffffu, inD[kk & 7], kk >> 3, 8);
        u64 vvA = pack2(vA, vA), vvB = pack2(vB, vB);
        u64 vvC = pack2(vC, vC), vvD = pack2(vD, vD);
        ulonglong2 w = *(const ulonglong2*)&sW1[kk * 32 + c0];
        ffma2(accA[0], w.x, vvA); ffma2(accA[1], w.y, vvA);
        ffma2(accB[0], w.x, vvB); ffma2(accB[1], w.y, vvB);
        ffma2(accC[0], w.x, vvC); ffma2(accC[1], w.y, vvC);
        ffma2(accD[0], w.x, vvD); ffma2(accD[1], w.y, vvD);
    }
    float hhA[4], hhB[4], hhC[4], hhD[4];
    {
        float t0, t1;
        unpack2(accA[0], t0, t1); hhA[0] = siluf(t0); hhA[1] = siluf(t1);
        unpack2(accA[1], t0, t1); hhA[2] = siluf(t0); hhA[3] = siluf(t1);
        unpack2(accB[0], t0, t1); hhB[0] = siluf(t0); hhB[1] = siluf(t1);
        unpack2(accB[1], t0, t1); hhB[2] = siluf(t0); hhB[3] = siluf(t1);
        unpack2(accC[0], t0, t1); hhC[0] = siluf(t0); hhC[1] = siluf(t1);
        unpack2(accC[1], t0, t1); hhC[2] = siluf(t0); hhC[3] = siluf(t1);
        unpack2(accD[0], t0, t1); hhD[0] = siluf(t0); hhD[1] = siluf(t1);
        unpack2(accD[1], t0, t1); hhD[2] = siluf(t0); hhD[3] = siluf(t1);
    }

    u64 a2A[2], a2B[2], a2C[2], a2D[2];
    {
        u64 b0 = pack2(cb2[c0], cb2[c0 + 1]);
        u64 b1 = pack2(cb2[c0 + 2], cb2[c0 + 3]);
        a2A[0] = b0; a2A[1] = b1; a2B[0] = b0; a2B[1] = b1;
        a2C[0] = b0; a2C[1] = b1; a2D[0] = b0; a2D[1] = b1;
    }
    MV32X4(a2A, a2B, a2C, a2D, hhA, hhB, hhC, hhD, sW2, c0);

    {
        float t0, t1, t2, t3;
        unpack2(a2A[0], t0, t1); unpack2(a2A[1], t2, t3);
        float4 xm = *(const float4*)&g_xm[n0 * 32 + c0];
        *(float4*)&outx[n0 * 32 + c0] = make_float4(
            siluf(xm.x + t0), siluf(xm.y + t1), siluf(xm.z + t2), siluf(xm.w + t3));
    }
    {
        int n = n0 + 1;
        float t0, t1, t2, t3;
        unpack2(a2B[0], t0, t1); unpack2(a2B[1], t2, t3);
        float4 xm = *(const float4*)&g_xm[n * 32 + c0];
        *(float4*)&outx[n * 32 + c0] = make_float4(
            siluf(xm.x + t0), siluf(xm.y + t1), siluf(xm.z + t2), siluf(xm.w + t3));
    }
    {
        int n = n0 + 2;
        float t0, t1, t2, t3;
        unpack2(a2C[0], t0, t1); unpack2(a2C[1], t2, t3);
        float4 xm = *(const float4*)&g_xm[n * 32 + c0];
        *(float4*)&outx[n * 32 + c0] = make_float4(
            siluf(xm.x + t0), siluf(xm.y + t1), siluf(xm.z + t2), siluf(xm.w + t3));
    }
    {
        int n = n0 + 3;
        float t0, t1, t2, t3;
        unpack2(a2D[0], t0, t1); unpack2(a2D[1], t2, t3);
        float4 xm = *(const float4*)&g_xm[n * 32 + c0];
        *(float4*)&outx[n * 32 + c0] = make_float4(
            siluf(xm.x + t0), siluf(xm.y + t1), siluf(xm.z + t2), siluf(xm.w + t3));
    }

    if (q < 4) {
        int n = n0 + q;
        float4 pa = *(const float4*)&g_pacc[n * 4];
        float ic = 1.0f / fmaxf(pa.w, 1.0f);
        outp[n * 3 + 0] = pos[n * 3 + 0] + pa.x * ic;
        outp[n * 3 + 1] = pos[n * 3 + 1] + pa.y * ic;
        outp[n * 3 + 2] = pos[n * 3 + 2] + pa.z * ic;
    }
}

// ---------------- launch ----------------
static int s_sm_count = 0;
static int s_blk_edge = 0;

extern "C" void kernel_launch(void* const* d_in, const int* in_sizes, int n_in,
                              void* d_out, int out_size) {
    const float* x        = (const float*)d_in[0];
    const int*   ei       = (const int*)d_in[1];
    const float* pos      = (const float*)d_in[2];
    const float* time     = (const float*)d_in[3];
    const int*   batch    = (const int*)d_in[4];
    const float* means    = (const float*)d_in[5];
    const float* betas    = (const float*)d_in[6];
    const float* w_dist   = (const float*)d_in[7];
    const float* msg_w1   = (const float*)d_in[8];
    const float* msg_b1   = (const float*)d_in[9];
    const float* msg_w2   = (const float*)d_in[10];
    const float* msg_b2   = (const float*)d_in[11];
    const float* gate_w   = (const float*)d_in[12];
    const float* gate_b   = (const float*)d_in[13];
    const float* time_w1  = (const float*)d_in[14];
    const float* time_b1  = (const float*)d_in[15];
    const float* time_w2  = (const float*)d_in[16];
    const float* time_b2  = (const float*)d_in[17];
    const float* comb_w1  = (const float*)d_in[18];
    const float* comb_b1  = (const float*)d_in[19];
    const float* comb_w2  = (const float*)d_in[20];
    const float* comb_b2  = (const float*)d_in[21];
    const float* coord_w1 = (const float*)d_in[22];
    const float* coord_b1 = (const float*)d_in[23];
    const float* coord_w2 = (const float*)d_in[24];
    const float* coord_b2 = (const float*)d_in[25];

    float* outx = (float*)d_out;
    float* outp = (float*)d_out + N_NODES * 32;

    if (s_sm_count == 0) {
        cudaDeviceGetAttribute(&s_sm_count, cudaDevAttrMultiProcessorCount, 0);
        int b;
        cudaOccupancyMaxActiveBlocksPerMultiprocessor(&b, k_edge, 128, 0);
        s_blk_edge = b > 0 ? b : 4;
    }
    int ge = s_sm_count * s_blk_edge;
    if (ge > EDGE_TILES) ge = EDGE_TILES;

    k_time<<<G_GRAPHS / 4 + TAB / 8, 256>>>(time, time_w1, time_b1, time_w2, time_b2,
                                            means, betas, w_dist);
    k_node<<<NODE_BLOCKS, 128>>>(x, batch, pos, msg_w1, msg_b1, gate_w, gate_b);
    k_edge<<<ge, 128>>>(ei, msg_w2, msg_b2,
                        coord_w1, coord_b1, coord_w2, coord_b2);
    k_final<<<NODE_BLOCKS, 128>>>(pos, comb_w1, comb_b1, comb_w2, comb_b2,
                                  outx, outp);
}